// round 1
// baseline (speedup 1.0000x reference)
#include <cuda_runtime.h>
#include <math.h>

// Problem constants
#define T_STEPS 512
#define B_SZ    64
#define F_SZ    128
#define H_SZ    512
#define O_SZ    16
#define G_SZ    (3 * H_SZ)   // 1536

// K2 persistent-kernel config
#define NCTA2   128
#define NTHR2   256
#define JPC     4            // h-units per CTA (512 / 128)

// ---------------------------------------------------------------------------
// Device scratch (allocation-free rule: __device__ globals)
// ---------------------------------------------------------------------------
__device__ float g_XG[T_STEPS * B_SZ * G_SZ];   // precomputed input-side gate preacts
__device__ float g_H[B_SZ * H_SZ];              // current hidden state
__device__ float g_HS[T_STEPS * B_SZ * H_SZ];   // all hidden states (for projection)
__device__ unsigned g_barCount = 0;
__device__ unsigned g_barSense = 0;

// ---------------------------------------------------------------------------
// K1: xg[m][g] = sum_f x[m][f] * w_ih[g][f] + b_ih[g]   (M=32768, N=1536, K=128)
// 64x64 tile, 256 threads, 4x4 register tile.
// ---------------------------------------------------------------------------
__global__ void __launch_bounds__(256, 2)
k1_xg(const float* __restrict__ x, const float* __restrict__ wih,
      const float* __restrict__ bih)
{
    __shared__ float As[32][68];   // As[k][m]
    __shared__ float Bs[32][68];   // Bs[k][n]

    const int tid = threadIdx.x;
    const int tx = tid & 15;       // n-tile
    const int ty = tid >> 4;       // m-tile
    const int m0 = blockIdx.y * 64;
    const int n0 = blockIdx.x * 64;

    float c[4][4];
#pragma unroll
    for (int i = 0; i < 4; i++)
#pragma unroll
        for (int j = 0; j < 4; j++) c[i][j] = 0.f;

    for (int kc = 0; kc < F_SZ; kc += 32) {
        __syncthreads();
#pragma unroll
        for (int i = 0; i < 2; i++) {
            int lin = tid + i * 256;           // 0..511
            int m = lin >> 3, k4 = lin & 7;
            float4 v = *(const float4*)&x[(m0 + m) * F_SZ + kc + k4 * 4];
            As[k4 * 4 + 0][m] = v.x; As[k4 * 4 + 1][m] = v.y;
            As[k4 * 4 + 2][m] = v.z; As[k4 * 4 + 3][m] = v.w;
        }
#pragma unroll
        for (int i = 0; i < 2; i++) {
            int lin = tid + i * 256;
            int n = lin >> 3, k4 = lin & 7;
            float4 v = *(const float4*)&wih[(n0 + n) * F_SZ + kc + k4 * 4];
            Bs[k4 * 4 + 0][n] = v.x; Bs[k4 * 4 + 1][n] = v.y;
            Bs[k4 * 4 + 2][n] = v.z; Bs[k4 * 4 + 3][n] = v.w;
        }
        __syncthreads();
#pragma unroll
        for (int k = 0; k < 32; k++) {
            float a[4], b[4];
#pragma unroll
            for (int i = 0; i < 4; i++) a[i] = As[k][ty * 4 + i];
#pragma unroll
            for (int j = 0; j < 4; j++) b[j] = Bs[k][tx * 4 + j];
#pragma unroll
            for (int i = 0; i < 4; i++)
#pragma unroll
                for (int j = 0; j < 4; j++)
                    c[i][j] = fmaf(a[i], b[j], c[i][j]);
        }
    }

    float bb[4];
#pragma unroll
    for (int j = 0; j < 4; j++) bb[j] = __ldg(&bih[n0 + tx * 4 + j]);
#pragma unroll
    for (int i = 0; i < 4; i++) {
        float4 v;
        v.x = c[i][0] + bb[0]; v.y = c[i][1] + bb[1];
        v.z = c[i][2] + bb[2]; v.w = c[i][3] + bb[3];
        *(float4*)&g_XG[(m0 + ty * 4 + i) * G_SZ + n0 + tx * 4] = v;
    }
}

// ---------------------------------------------------------------------------
// Grid-wide sense-reversing barrier (all NCTA2 CTAs co-resident).
// Exactly 512 barriers per launch -> sense returns to 0 for graph replays.
// ---------------------------------------------------------------------------
__device__ __forceinline__ void grid_barrier(unsigned ns)
{
    if (threadIdx.x == 0) {
        if (atomicAdd(&g_barCount, 1u) == (unsigned)(gridDim.x - 1)) {
            atomicExch(&g_barCount, 0u);
            __threadfence();
            atomicExch(&g_barSense, ns);
        } else {
            while (*((volatile unsigned*)&g_barSense) != ns) { }
            __threadfence();
        }
    }
    __syncthreads();
}

__device__ __forceinline__ float sigmoidf_(float v)
{
    return 1.0f / (1.0f + expf(-v));
}

// ---------------------------------------------------------------------------
// K2: persistent GRU recurrence. CTA c owns j in [4c, 4c+4).
// Thread map: q = tid&3 (j idx), bg = (tid>>2)&15 (batch group of 4), ks = tid>>6.
// ---------------------------------------------------------------------------
__global__ void __launch_bounds__(NTHR2, 1)
k2_gru(const float* __restrict__ wHH, const float* __restrict__ bHH)
{
    __shared__ float Ws[H_SZ * 12];       // Ws[k*12 + g*4 + q]  (24576 B)
    __shared__ float Bh[12];
    __shared__ float Hs[B_SZ * 33];       // chunk of h: Hs[b*33 + kk] (8448 B)
    __shared__ float Red[4 * 64 * 12];    // k-split partials      (12288 B)

    const int tid = threadIdx.x;
    const int q  = tid & 3;
    const int bg = (tid >> 2) & 15;
    const int ks = tid >> 6;              // 0..3
    const int b0 = bg * 4;
    const int jbase = blockIdx.x * JPC;
    const int j = jbase + q;

    // Load this CTA's 12 w_hh rows into SMEM (persistent for all 512 steps)
#pragma unroll
    for (int i = 0; i < 24; i++) {
        int lin = tid + i * 256;          // 0..6143
        int k = lin & 511;
        int r = lin >> 9;                 // 0..11 == g*4+q
        int g = r >> 2, qq = r & 3;
        Ws[k * 12 + r] = wHH[(g * H_SZ + jbase + qq) * H_SZ + k];
    }
    if (tid < 12) {
        int g = tid >> 2, qq = tid & 3;
        Bh[tid] = bHH[g * H_SZ + jbase + qq];
    }
    __syncthreads();

    for (int t = 0; t < T_STEPS; t++) {
        float acc0[4], acc1[4], acc2[4];
#pragma unroll
        for (int i = 0; i < 4; i++) { acc0[i] = 0.f; acc1[i] = 0.f; acc2[i] = 0.f; }

        if (t > 0) {
            for (int kc = 0; kc < H_SZ; kc += 32) {
                __syncthreads();
#pragma unroll
                for (int i = 0; i < 8; i++) {
                    int lin = tid + i * 256;   // 0..2047
                    int b = lin >> 5, jj = lin & 31;
                    Hs[b * 33 + jj] = __ldcg(&g_H[b * H_SZ + kc + jj]);
                }
                __syncthreads();
                const float* wsBase = &Ws[(kc + ks * 8) * 12];
#pragma unroll
                for (int kk = 0; kk < 8; kk++) {
                    float w0 = wsBase[kk * 12 + 0 + q];
                    float w1 = wsBase[kk * 12 + 4 + q];
                    float w2 = wsBase[kk * 12 + 8 + q];
                    int hb = ks * 8 + kk;
#pragma unroll
                    for (int i = 0; i < 4; i++) {
                        float hv = Hs[(b0 + i) * 33 + hb];
                        acc0[i] = fmaf(w0, hv, acc0[i]);
                        acc1[i] = fmaf(w1, hv, acc1[i]);
                        acc2[i] = fmaf(w2, hv, acc2[i]);
                    }
                }
            }
        }

        // k-split reduction across ks=0..3
        __syncthreads();
        {
            int rem = tid & 63;
            float* my = &Red[(ks * 64 + rem) * 12];
#pragma unroll
            for (int i = 0; i < 4; i++) { my[i] = acc0[i]; my[4 + i] = acc1[i]; my[8 + i] = acc2[i]; }
        }
        __syncthreads();

        if (ks == 0) {
            int rem = tid & 63;
            float hr[4], hz[4], hn[4];
#pragma unroll
            for (int i = 0; i < 4; i++) { hr[i] = acc0[i]; hz[i] = acc1[i]; hn[i] = acc2[i]; }
#pragma unroll
            for (int s = 1; s < 4; s++) {
                const float* p = &Red[(s * 64 + rem) * 12];
#pragma unroll
                for (int i = 0; i < 4; i++) { hr[i] += p[i]; hz[i] += p[4 + i]; hn[i] += p[8 + i]; }
            }
            float bR = Bh[0 + q], bZ = Bh[4 + q], bN = Bh[8 + q];
#pragma unroll
            for (int i = 0; i < 4; i++) {
                int b = b0 + i;
                int base = (t * B_SZ + b) * G_SZ;
                float xr = __ldg(&g_XG[base + j]);
                float xz = __ldg(&g_XG[base + H_SZ + j]);
                float xn = __ldg(&g_XG[base + 2 * H_SZ + j]);
                float hprev = (t == 0) ? 0.f : __ldcg(&g_H[b * H_SZ + j]);
                float r = sigmoidf_(xr + hr[i] + bR);
                float z = sigmoidf_(xz + hz[i] + bZ);
                float n = tanhf(xn + r * (hn[i] + bN));
                float hnew = (1.0f - z) * n + z * hprev;
                __stcg(&g_H[b * H_SZ + j], hnew);
                g_HS[(t * B_SZ + b) * H_SZ + j] = hnew;
            }
            __threadfence();
        }
        __syncthreads();
        grid_barrier((unsigned)(t & 1) ^ 1u);   // t=0 -> 1, ..., t=511 -> 0 (back to init)
    }
}

// ---------------------------------------------------------------------------
// K3: y[m][o] = sum_j HS[m][j] * w_out[o][j] + b_out[o]   (M=32768, N=16, K=512)
// 128x16 tile, 128 threads, 4x4 register tiles.
// ---------------------------------------------------------------------------
__global__ void __launch_bounds__(128, 4)
k3_out(const float* __restrict__ wout, const float* __restrict__ bout,
       float* __restrict__ y)
{
    __shared__ float As[32][132];   // As[k][m]
    __shared__ float Wsh[32][16];   // Wsh[k][n]

    const int tid = threadIdx.x;
    const int tx = tid & 3;         // n tile (4 groups of 4)
    const int ty = tid >> 2;        // m tile (32 groups of 4)
    const int m0 = blockIdx.x * 128;

    float c[4][4];
#pragma unroll
    for (int i = 0; i < 4; i++)
#pragma unroll
        for (int jj = 0; jj < 4; jj++) c[i][jj] = 0.f;

    for (int kc = 0; kc < H_SZ; kc += 32) {
        __syncthreads();
#pragma unroll
        for (int i = 0; i < 8; i++) {
            int lin = tid + i * 128;           // 0..1023
            int m = lin >> 3, k4 = lin & 7;
            float4 v = *(const float4*)&g_HS[(m0 + m) * H_SZ + kc + k4 * 4];
            As[k4 * 4 + 0][m] = v.x; As[k4 * 4 + 1][m] = v.y;
            As[k4 * 4 + 2][m] = v.z; As[k4 * 4 + 3][m] = v.w;
        }
#pragma unroll
        for (int i = 0; i < 4; i++) {
            int lin = tid + i * 128;           // 0..511
            int n = lin >> 5, k = lin & 31;
            Wsh[k][n] = wout[n * H_SZ + kc + k];
        }
        __syncthreads();
#pragma unroll
        for (int k = 0; k < 32; k++) {
            float a[4], w[4];
#pragma unroll
            for (int i = 0; i < 4; i++) a[i] = As[k][ty * 4 + i];
#pragma unroll
            for (int jj = 0; jj < 4; jj++) w[jj] = Wsh[k][tx * 4 + jj];
#pragma unroll
            for (int i = 0; i < 4; i++)
#pragma unroll
                for (int jj = 0; jj < 4; jj++)
                    c[i][jj] = fmaf(a[i], w[jj], c[i][jj]);
        }
    }

    float bb[4];
#pragma unroll
    for (int jj = 0; jj < 4; jj++) bb[jj] = __ldg(&bout[tx * 4 + jj]);
#pragma unroll
    for (int i = 0; i < 4; i++) {
        float4 v;
        v.x = c[i][0] + bb[0]; v.y = c[i][1] + bb[1];
        v.z = c[i][2] + bb[2]; v.w = c[i][3] + bb[3];
        *(float4*)&y[(m0 + ty * 4 + i) * O_SZ + tx * 4] = v;
    }
}

// ---------------------------------------------------------------------------
// Entry point
// ---------------------------------------------------------------------------
extern "C" void kernel_launch(void* const* d_in, const int* in_sizes, int n_in,
                              void* d_out, int out_size)
{
    const float* x    = (const float*)d_in[0];   // (T,B,F)
    const float* wih  = (const float*)d_in[1];   // (3H,F)
    const float* whh  = (const float*)d_in[2];   // (3H,H)
    const float* bih  = (const float*)d_in[3];   // (3H)
    const float* bhh  = (const float*)d_in[4];   // (3H)
    const float* wout = (const float*)d_in[5];   // (O,H)
    const float* bout = (const float*)d_in[6];   // (O)
    float* y = (float*)d_out;                    // (T,B,O)

    // 1) xg = x @ w_ih^T + b_ih  (parallel over all T*B)
    k1_xg<<<dim3(G_SZ / 64, (T_STEPS * B_SZ) / 64), 256>>>(x, wih, bih);

    // 2) persistent GRU recurrence over T steps (grid-wide barrier per step)
    k2_gru<<<NCTA2, NTHR2>>>(whh, bhh);

    // 3) output projection
    k3_out<<<(T_STEPS * B_SZ) / 128, 128>>>(wout, bout, y);
}

// round 2
// speedup vs baseline: 1.2018x; 1.2018x over previous
#include <cuda_runtime.h>
#include <math.h>

// Problem constants
#define T_STEPS 512
#define B_SZ    64
#define F_SZ    128
#define H_SZ    512
#define O_SZ    16
#define G_SZ    (3 * H_SZ)   // 1536

// K2 persistent-kernel config
#define NCTA2   128
#define NTHR2   256
#define JPC     4            // h-units per CTA (512 / 128)

// K2 dynamic SMEM: Ws (512*12 floats) + Red (12*4*16*16 floats)
#define WS_FLOATS   (H_SZ * 12)          // 6144
#define RED_FLOATS  (12 * 4 * 16 * 16)   // 12288
#define SMEM2_BYTES ((WS_FLOATS + RED_FLOATS) * 4)   // 73728

// ---------------------------------------------------------------------------
// Device scratch (allocation-free rule: __device__ globals)
// ---------------------------------------------------------------------------
__device__ float g_XG[T_STEPS * B_SZ * G_SZ];     // input-side gate preacts
__device__ float g_H2[2][H_SZ * B_SZ];            // double-buffered h, layout [j][b]
__device__ float g_HS[T_STEPS * B_SZ * H_SZ];     // all hidden states (for K3)
__device__ unsigned g_flags[NCTA2];               // per-CTA step flags (zero-init)
__device__ unsigned g_cnt = 0;                    // end-of-kernel counter barrier
__device__ unsigned g_sense = 0;

// ---------------------------------------------------------------------------
// f32x2 packed helpers (FFMA2 — ptxas won't auto-fuse; PTX only)
// ---------------------------------------------------------------------------
__device__ __forceinline__ unsigned long long pk2(float a, float b) {
    unsigned long long r;
    asm("mov.b64 %0, {%1, %2};" : "=l"(r) : "f"(a), "f"(b));
    return r;
}
__device__ __forceinline__ void upk2(unsigned long long v, float& a, float& b) {
    asm("mov.b64 {%0, %1}, %2;" : "=f"(a), "=f"(b) : "l"(v));
}
__device__ __forceinline__ unsigned long long fma2(unsigned long long a,
                                                   unsigned long long b,
                                                   unsigned long long c) {
    unsigned long long d;
    asm("fma.rn.f32x2 %0, %1, %2, %3;" : "=l"(d) : "l"(a), "l"(b), "l"(c));
    return d;
}

__device__ __forceinline__ float fsig(float x) {
    return 1.0f / (1.0f + __expf(-x));
}

// ---------------------------------------------------------------------------
// K1: xg[m][g] = sum_f x[m][f] * w_ih[g][f] + b_ih[g]   (M=32768, N=1536, K=128)
// ---------------------------------------------------------------------------
__global__ void __launch_bounds__(256, 2)
k1_xg(const float* __restrict__ x, const float* __restrict__ wih,
      const float* __restrict__ bih)
{
    __shared__ float As[32][68];   // As[k][m]
    __shared__ float Bs[32][68];   // Bs[k][n]

    const int tid = threadIdx.x;
    const int tx = tid & 15;
    const int ty = tid >> 4;
    const int m0 = blockIdx.y * 64;
    const int n0 = blockIdx.x * 64;

    float c[4][4];
#pragma unroll
    for (int i = 0; i < 4; i++)
#pragma unroll
        for (int j = 0; j < 4; j++) c[i][j] = 0.f;

    for (int kc = 0; kc < F_SZ; kc += 32) {
        __syncthreads();
#pragma unroll
        for (int i = 0; i < 2; i++) {
            int lin = tid + i * 256;
            int m = lin >> 3, k4 = lin & 7;
            float4 v = *(const float4*)&x[(m0 + m) * F_SZ + kc + k4 * 4];
            As[k4 * 4 + 0][m] = v.x; As[k4 * 4 + 1][m] = v.y;
            As[k4 * 4 + 2][m] = v.z; As[k4 * 4 + 3][m] = v.w;
        }
#pragma unroll
        for (int i = 0; i < 2; i++) {
            int lin = tid + i * 256;
            int n = lin >> 3, k4 = lin & 7;
            float4 v = *(const float4*)&wih[(n0 + n) * F_SZ + kc + k4 * 4];
            Bs[k4 * 4 + 0][n] = v.x; Bs[k4 * 4 + 1][n] = v.y;
            Bs[k4 * 4 + 2][n] = v.z; Bs[k4 * 4 + 3][n] = v.w;
        }
        __syncthreads();
#pragma unroll
        for (int k = 0; k < 32; k++) {
            float a[4], b[4];
#pragma unroll
            for (int i = 0; i < 4; i++) a[i] = As[k][ty * 4 + i];
#pragma unroll
            for (int j = 0; j < 4; j++) b[j] = Bs[k][tx * 4 + j];
#pragma unroll
            for (int i = 0; i < 4; i++)
#pragma unroll
                for (int j = 0; j < 4; j++)
                    c[i][j] = fmaf(a[i], b[j], c[i][j]);
        }
    }

    float bb[4];
#pragma unroll
    for (int j = 0; j < 4; j++) bb[j] = __ldg(&bih[n0 + tx * 4 + j]);
#pragma unroll
    for (int i = 0; i < 4; i++) {
        float4 v;
        v.x = c[i][0] + bb[0]; v.y = c[i][1] + bb[1];
        v.z = c[i][2] + bb[2]; v.w = c[i][3] + bb[3];
        *(float4*)&g_XG[(m0 + ty * 4 + i) * G_SZ + n0 + tx * 4] = v;
    }
}

// ---------------------------------------------------------------------------
// End-of-kernel counter barrier (used exactly twice; sense returns to 0)
// ---------------------------------------------------------------------------
__device__ __forceinline__ void cbar(unsigned target)
{
    if (threadIdx.x == 0) {
        if (atomicAdd(&g_cnt, 1u) == (unsigned)(NCTA2 - 1)) {
            atomicExch(&g_cnt, 0u);
            __threadfence();
            atomicExch(&g_sense, target);
        } else {
            while (*((volatile unsigned*)&g_sense) != target) { }
            __threadfence();
        }
    }
    __syncthreads();
}

// ---------------------------------------------------------------------------
// K2: persistent GRU recurrence.
// CTA owns 4 h-units (12 gate rows). Threads: bg = tid&15 (4 batches each),
// ks = tid>>4 (k-slice of 32). Per thread: 12x4 f32x2 register tile, k-split
// 16 reduced through SMEM. Double-buffered h; flag-array barrier per step.
// ---------------------------------------------------------------------------
__global__ void __launch_bounds__(NTHR2, 1)
k2_gru(const float* __restrict__ wHH, const float* __restrict__ bHH)
{
    extern __shared__ float sm[];
    float* Ws  = sm;               // Ws[k*12 + r], r = g*4 + q
    float* Red = sm + WS_FLOATS;   // Red[r*1024 + i*256 + bg*16 + ks]

    const int tid = threadIdx.x;
    const int bid = blockIdx.x;
    const int bg = tid & 15;
    const int ks = tid >> 4;
    const int jbase = bid * JPC;

    // epilogue mapping: thread -> (q, b)
    const int eq = tid >> 6;        // 0..3 (h-unit within CTA)
    const int eb = tid & 63;        // batch
    const int ej = jbase + eq;

    // Load weights into SMEM once (coalesced global reads)
    for (int idx = tid; idx < WS_FLOATS; idx += NTHR2) {
        int r = idx >> 9, k = idx & 511;
        int g = r >> 2, q = r & 3;
        Ws[k * 12 + r] = wHH[(g * H_SZ + jbase + q) * H_SZ + k];
    }
    const float bR = __ldg(&bHH[0 * H_SZ + ej]);
    const float bZ = __ldg(&bHH[1 * H_SZ + ej]);
    const float bN = __ldg(&bHH[2 * H_SZ + ej]);
    __syncthreads();

    volatile unsigned* vflags = (volatile unsigned*)g_flags;

    for (int t = 0; t < T_STEPS; t++) {
        // --- barrier: wait until all CTAs committed step t-1 ---
        if (t > 0) {
            if (tid < NCTA2) {
                while (vflags[tid] < (unsigned)t) { }
            }
            __syncthreads();   // also protects Red reuse (prev epilogue reads done)
        }

        const float* hRead = g_H2[(t + 1) & 1];   // holds h(t-1)
        float*       hWrit = g_H2[t & 1];         // receives h(t)

        unsigned long long acc[12][2];
#pragma unroll
        for (int r = 0; r < 12; r++) { acc[r][0] = 0ull; acc[r][1] = 0ull; }

        if (t > 0) {
            // 8-deep register prefetch of this thread's private h slice
            float4 hbuf[8];
#pragma unroll
            for (int p = 0; p < 8; p++)
                hbuf[p] = __ldcg((const float4*)&hRead[(ks * 32 + p) * 64 + bg * 4]);

#pragma unroll 8
            for (int kk = 0; kk < 32; kk++) {
                float4 h4 = hbuf[kk & 7];
                if (kk < 24)
                    hbuf[kk & 7] = __ldcg((const float4*)&hRead[(ks * 32 + kk + 8) * 64 + bg * 4]);

                unsigned long long hlo = pk2(h4.x, h4.y);
                unsigned long long hhi = pk2(h4.z, h4.w);

                const float4* wp = (const float4*)&Ws[(ks * 32 + kk) * 12];
                float4 w0 = wp[0], w1 = wp[1], w2 = wp[2];
                float wv[12] = { w0.x, w0.y, w0.z, w0.w,
                                 w1.x, w1.y, w1.z, w1.w,
                                 w2.x, w2.y, w2.z, w2.w };
#pragma unroll
                for (int r = 0; r < 12; r++) {
                    unsigned long long wd = pk2(wv[r], wv[r]);
                    acc[r][0] = fma2(wd, hlo, acc[r][0]);
                    acc[r][1] = fma2(wd, hhi, acc[r][1]);
                }
            }
        }

        // --- write k-split partials ---
#pragma unroll
        for (int r = 0; r < 12; r++) {
            float v0, v1, v2, v3;
            upk2(acc[r][0], v0, v1);
            upk2(acc[r][1], v2, v3);
            int base = r * 1024 + bg * 16 + ks;
            Red[base        ] = v0;
            Red[base +  256 ] = v1;
            Red[base +  512 ] = v2;
            Red[base +  768 ] = v3;
        }
        __syncthreads();

        // --- reduce 16 partials + gates + h update (thread = (eq, eb)) ---
        float s[3];
#pragma unroll
        for (int g = 0; g < 3; g++) {
            int r = g * 4 + eq;
            const float4* p = (const float4*)&Red[r * 1024 + (eb & 3) * 256 + (eb >> 2) * 16];
            float4 a = p[0], b = p[1], c = p[2], d = p[3];
            s[g] = ((a.x + a.y) + (a.z + a.w)) + ((b.x + b.y) + (b.z + b.w))
                 + ((c.x + c.y) + (c.z + c.w)) + ((d.x + d.y) + (d.z + d.w));
        }

        const float* xg = &g_XG[(t * B_SZ + eb) * G_SZ];
        float xr = __ldg(&xg[ej]);
        float xz = __ldg(&xg[H_SZ + ej]);
        float xn = __ldg(&xg[2 * H_SZ + ej]);
        float hprev = (t > 0) ? __ldcg(&hRead[ej * 64 + eb]) : 0.f;

        float rg = fsig(xr + s[0] + bR);
        float zg = fsig(xz + s[1] + bZ);
        float ng = tanhf(xn + rg * (s[2] + bN));
        float hnew = (1.0f - zg) * ng + zg * hprev;

        __stcg(&hWrit[ej * 64 + eb], hnew);
        g_HS[(t * B_SZ + eb) * H_SZ + ej] = hnew;

        __threadfence();
        __syncthreads();
        if (tid == 0) vflags[bid] = (unsigned)(t + 1);
    }

    // --- replay-safe flag reset ---
    if (tid < NCTA2) {
        while (vflags[tid] < (unsigned)T_STEPS) { }
    }
    __syncthreads();
    cbar(1u);                       // everyone past final wait
    if (tid == 0) vflags[bid] = 0u;
    __threadfence();
    cbar(0u);                       // sense back to initial state
}

// ---------------------------------------------------------------------------
// K3: y[m][o] = sum_j HS[m][j] * w_out[o][j] + b_out[o]   (M=32768, N=16, K=512)
// ---------------------------------------------------------------------------
__global__ void __launch_bounds__(128, 4)
k3_out(const float* __restrict__ wout, const float* __restrict__ bout,
       float* __restrict__ y)
{
    __shared__ float As[32][132];
    __shared__ float Wsh[32][16];

    const int tid = threadIdx.x;
    const int tx = tid & 3;
    const int ty = tid >> 2;
    const int m0 = blockIdx.x * 128;

    float c[4][4];
#pragma unroll
    for (int i = 0; i < 4; i++)
#pragma unroll
        for (int jj = 0; jj < 4; jj++) c[i][jj] = 0.f;

    for (int kc = 0; kc < H_SZ; kc += 32) {
        __syncthreads();
#pragma unroll
        for (int i = 0; i < 8; i++) {
            int lin = tid + i * 128;
            int m = lin >> 3, k4 = lin & 7;
            float4 v = *(const float4*)&g_HS[(m0 + m) * H_SZ + kc + k4 * 4];
            As[k4 * 4 + 0][m] = v.x; As[k4 * 4 + 1][m] = v.y;
            As[k4 * 4 + 2][m] = v.z; As[k4 * 4 + 3][m] = v.w;
        }
#pragma unroll
        for (int i = 0; i < 4; i++) {
            int lin = tid + i * 128;
            int n = lin >> 5, k = lin & 31;
            Wsh[k][n] = wout[n * H_SZ + kc + k];
        }
        __syncthreads();
#pragma unroll
        for (int k = 0; k < 32; k++) {
            float a[4], w[4];
#pragma unroll
            for (int i = 0; i < 4; i++) a[i] = As[k][ty * 4 + i];
#pragma unroll
            for (int jj = 0; jj < 4; jj++) w[jj] = Wsh[k][tx * 4 + jj];
#pragma unroll
            for (int i = 0; i < 4; i++)
#pragma unroll
                for (int jj = 0; jj < 4; jj++)
                    c[i][jj] = fmaf(a[i], w[jj], c[i][jj]);
        }
    }

    float bb[4];
#pragma unroll
    for (int jj = 0; jj < 4; jj++) bb[jj] = __ldg(&bout[tx * 4 + jj]);
#pragma unroll
    for (int i = 0; i < 4; i++) {
        float4 v;
        v.x = c[i][0] + bb[0]; v.y = c[i][1] + bb[1];
        v.z = c[i][2] + bb[2]; v.w = c[i][3] + bb[3];
        *(float4*)&y[(m0 + ty * 4 + i) * O_SZ + tx * 4] = v;
    }
}

// ---------------------------------------------------------------------------
// Entry point
// ---------------------------------------------------------------------------
extern "C" void kernel_launch(void* const* d_in, const int* in_sizes, int n_in,
                              void* d_out, int out_size)
{
    const float* x    = (const float*)d_in[0];   // (T,B,F)
    const float* wih  = (const float*)d_in[1];   // (3H,F)
    const float* whh  = (const float*)d_in[2];   // (3H,H)
    const float* bih  = (const float*)d_in[3];   // (3H)
    const float* bhh  = (const float*)d_in[4];   // (3H)
    const float* wout = (const float*)d_in[5];   // (O,H)
    const float* bout = (const float*)d_in[6];   // (O)
    float* y = (float*)d_out;                    // (T,B,O)

    // Opt-in to >48KB dynamic SMEM for K2 (host-side attr, not captured)
    cudaFuncSetAttribute(k2_gru, cudaFuncAttributeMaxDynamicSharedMemorySize,
                         SMEM2_BYTES);

    // 1) xg = x @ w_ih^T + b_ih
    k1_xg<<<dim3(G_SZ / 64, (T_STEPS * B_SZ) / 64), 256>>>(x, wih, bih);

    // 2) persistent GRU recurrence
    k2_gru<<<NCTA2, NTHR2, SMEM2_BYTES>>>(whh, bhh);

    // 3) output projection
    k3_out<<<(T_STEPS * B_SZ) / 128, 128>>>(wout, bout, y);
}

// round 3
// speedup vs baseline: 2.5291x; 2.1045x over previous
#include <cuda_runtime.h>
#include <math.h>

// Problem constants
#define T_STEPS 512
#define B_SZ    64
#define F_SZ    128
#define H_SZ    512
#define O_SZ    16
#define G_SZ    (3 * H_SZ)   // 1536

// K2 persistent-kernel config
#define NCTA2   128
#define NTHR2   256
#define JPC     4            // h-units per CTA (512 / 128)

// K2 dynamic SMEM: Ws (512*12 floats) + Red (12*4*16*17 floats)
#define WS_FLOATS   (H_SZ * 12)            // 6144
#define RED_FLOATS  (12 * 4 * 16 * 17)     // 13056
#define SMEM2_BYTES ((WS_FLOATS + RED_FLOATS) * 4)   // 76800

// ---------------------------------------------------------------------------
// Device scratch (allocation-free rule: __device__ globals)
// ---------------------------------------------------------------------------
__device__ float g_XG[T_STEPS * B_SZ * G_SZ];     // input-side gate preacts
__device__ float g_H2[2][H_SZ * B_SZ];            // double-buffered h, layout [j][b]
__device__ float g_HS[T_STEPS * B_SZ * H_SZ];     // all hidden states (for K3)
__device__ unsigned g_arrive = 0;                 // grid barrier arrival counter
__device__ unsigned g_cnt = 0;                    // end-of-kernel reset counter

// ---------------------------------------------------------------------------
// f32x2 packed helpers (FFMA2 — ptxas won't auto-fuse; PTX only)
// ---------------------------------------------------------------------------
__device__ __forceinline__ unsigned long long pk2(float a, float b) {
    unsigned long long r;
    asm("mov.b64 %0, {%1, %2};" : "=l"(r) : "f"(a), "f"(b));
    return r;
}
__device__ __forceinline__ void upk2(unsigned long long v, float& a, float& b) {
    asm("mov.b64 {%0, %1}, %2;" : "=f"(a), "=f"(b) : "l"(v));
}
__device__ __forceinline__ unsigned long long fma2(unsigned long long a,
                                                   unsigned long long b,
                                                   unsigned long long c) {
    unsigned long long d;
    asm("fma.rn.f32x2 %0, %1, %2, %3;" : "=l"(d) : "l"(a), "l"(b), "l"(c));
    return d;
}

__device__ __forceinline__ float fsig(float x) {
    return 1.0f / (1.0f + __expf(-x));
}

// ---------------------------------------------------------------------------
// K1: xg[m][g] = sum_f x[m][f] * w_ih[g][f] + b_ih[g]   (M=32768, N=1536, K=128)
// FFMA2 inner: pack n-pairs from Bs, duplicate a.
// ---------------------------------------------------------------------------
__global__ void __launch_bounds__(256, 2)
k1_xg(const float* __restrict__ x, const float* __restrict__ wih,
      const float* __restrict__ bih)
{
    __shared__ float As[32][68];   // As[k][m]
    __shared__ float Bs[32][68];   // Bs[k][n]

    const int tid = threadIdx.x;
    const int tx = tid & 15;
    const int ty = tid >> 4;
    const int m0 = blockIdx.y * 64;
    const int n0 = blockIdx.x * 64;

    unsigned long long c2[4][2];
#pragma unroll
    for (int i = 0; i < 4; i++) { c2[i][0] = 0ull; c2[i][1] = 0ull; }

    for (int kc = 0; kc < F_SZ; kc += 32) {
        __syncthreads();
#pragma unroll
        for (int i = 0; i < 2; i++) {
            int lin = tid + i * 256;
            int m = lin >> 3, k4 = lin & 7;
            float4 v = *(const float4*)&x[(m0 + m) * F_SZ + kc + k4 * 4];
            As[k4 * 4 + 0][m] = v.x; As[k4 * 4 + 1][m] = v.y;
            As[k4 * 4 + 2][m] = v.z; As[k4 * 4 + 3][m] = v.w;
        }
#pragma unroll
        for (int i = 0; i < 2; i++) {
            int lin = tid + i * 256;
            int n = lin >> 3, k4 = lin & 7;
            float4 v = *(const float4*)&wih[(n0 + n) * F_SZ + kc + k4 * 4];
            Bs[k4 * 4 + 0][n] = v.x; Bs[k4 * 4 + 1][n] = v.y;
            Bs[k4 * 4 + 2][n] = v.z; Bs[k4 * 4 + 3][n] = v.w;
        }
        __syncthreads();
#pragma unroll
        for (int k = 0; k < 32; k++) {
            float4 a4 = *(const float4*)&As[k][ty * 4];
            ulonglong2 b2 = *(const ulonglong2*)&Bs[k][tx * 4];
            unsigned long long ad[4];
            ad[0] = pk2(a4.x, a4.x); ad[1] = pk2(a4.y, a4.y);
            ad[2] = pk2(a4.z, a4.z); ad[3] = pk2(a4.w, a4.w);
#pragma unroll
            for (int i = 0; i < 4; i++) {
                c2[i][0] = fma2(ad[i], b2.x, c2[i][0]);
                c2[i][1] = fma2(ad[i], b2.y, c2[i][1]);
            }
        }
    }

    float bb[4];
#pragma unroll
    for (int j = 0; j < 4; j++) bb[j] = __ldg(&bih[n0 + tx * 4 + j]);
#pragma unroll
    for (int i = 0; i < 4; i++) {
        float4 v;
        upk2(c2[i][0], v.x, v.y);
        upk2(c2[i][1], v.z, v.w);
        v.x += bb[0]; v.y += bb[1]; v.z += bb[2]; v.w += bb[3];
        *(float4*)&g_XG[(m0 + ty * 4 + i) * G_SZ + n0 + tx * 4] = v;
    }
}

// ---------------------------------------------------------------------------
// K2: persistent GRU recurrence.
// CTA owns 4 h-units (12 gate rows). Main loop: bg = tid&15 (4 batches),
// ks = tid>>4 (k-slice of 32). Weight j-pairs via ulonglong2 LDS, h duplicated.
// Grid sync: single release-add arrival counter + acquire poll by tid0.
// ---------------------------------------------------------------------------
__global__ void __launch_bounds__(NTHR2, 1)
k2_gru(const float* __restrict__ wHH, const float* __restrict__ bHH)
{
    extern __shared__ float sm[];
    float* Ws  = sm;               // Ws[k*12 + r], r = g*4 + q (48B/row, 16B-aligned)
    float* Red = sm + WS_FLOATS;   // Red[((r*4 + i)*16 + bg)*17 + ks]

    const int tid = threadIdx.x;
    const int bid = blockIdx.x;
    const int bg = tid & 15;
    const int ks = tid >> 4;
    const int jbase = bid * JPC;

    // epilogue mapping: thread -> (q, b)
    const int eq = tid >> 6;        // 0..3 (h-unit within CTA)
    const int eb = tid & 63;        // batch
    const int ej = jbase + eq;
    const int ei = eb & 3;          // batch-within-group
    const int ebg = eb >> 2;        // batch group

    // Load weights into SMEM once
    for (int idx = tid; idx < WS_FLOATS; idx += NTHR2) {
        int r = idx >> 9, k = idx & 511;
        int g = r >> 2, q = r & 3;
        Ws[k * 12 + r] = wHH[(g * H_SZ + jbase + q) * H_SZ + k];
    }
    const float bR = __ldg(&bHH[0 * H_SZ + ej]);
    const float bZ = __ldg(&bHH[1 * H_SZ + ej]);
    const float bN = __ldg(&bHH[2 * H_SZ + ej]);
    __syncthreads();

    unsigned* arr = &g_arrive;

    for (int t = 0; t < T_STEPS; t++) {
        // --- prefetch this step's XG (independent of h; hides DRAM latency) ---
        const float* xg = &g_XG[(t * B_SZ + eb) * G_SZ];
        float xr = __ldg(&xg[ej]);
        float xz = __ldg(&xg[H_SZ + ej]);
        float xn = __ldg(&xg[2 * H_SZ + ej]);

        // --- grid barrier: wait for all arrivals of step t-1 ---
        if (t > 0) {
            if (tid == 0) {
                unsigned target = (unsigned)NCTA2 * (unsigned)t;
                unsigned v;
                do {
                    asm volatile("ld.acquire.gpu.u32 %0, [%1];"
                                 : "=r"(v) : "l"(arr) : "memory");
                } while (v < target);
            }
            __syncthreads();   // releases CTA; also protects Red reuse
        }

        const float* hRead = g_H2[(t + 1) & 1];   // h(t-1)
        float*       hWrit = g_H2[t & 1];         // h(t)

        unsigned long long acc[6][4];
#pragma unroll
        for (int rp = 0; rp < 6; rp++)
#pragma unroll
            for (int i = 0; i < 4; i++) acc[rp][i] = 0ull;

        float hprev = 0.f;
        if (t > 0) {
            hprev = __ldcg(&hRead[ej * 64 + eb]);

            float4 hbuf[4];
#pragma unroll
            for (int p = 0; p < 4; p++)
                hbuf[p] = __ldcg((const float4*)&hRead[(ks * 32 + p) * 64 + bg * 4]);

#pragma unroll 4
            for (int kk = 0; kk < 32; kk++) {
                float4 h4 = hbuf[kk & 3];
                if (kk < 28)
                    hbuf[kk & 3] = __ldcg((const float4*)&hRead[(ks * 32 + kk + 4) * 64 + bg * 4]);

                unsigned long long hh[4];
                hh[0] = pk2(h4.x, h4.x); hh[1] = pk2(h4.y, h4.y);
                hh[2] = pk2(h4.z, h4.z); hh[3] = pk2(h4.w, h4.w);

                const ulonglong2* wp = (const ulonglong2*)&Ws[(ks * 32 + kk) * 12];
                ulonglong2 wA = wp[0], wB = wp[1], wC = wp[2];
                unsigned long long wv[6] = { wA.x, wA.y, wB.x, wB.y, wC.x, wC.y };
#pragma unroll
                for (int rp = 0; rp < 6; rp++)
#pragma unroll
                    for (int i = 0; i < 4; i++)
                        acc[rp][i] = fma2(wv[rp], hh[i], acc[rp][i]);
            }
        }

        // --- k-split partials to SMEM (conflict-free: banks = 17*bg + ks) ---
#pragma unroll
        for (int rp = 0; rp < 6; rp++)
#pragma unroll
            for (int i = 0; i < 4; i++) {
                float v0, v1;
                upk2(acc[rp][i], v0, v1);
                int r0 = rp * 2;
                Red[(((r0    ) * 4 + i) * 16 + bg) * 17 + ks] = v0;
                Red[(((r0 + 1) * 4 + i) * 16 + bg) * 17 + ks] = v1;
            }
        __syncthreads();

        // --- reduce 16 partials + gates + h update (thread = (eq, eb)) ---
        float s[3];
#pragma unroll
        for (int g = 0; g < 3; g++) {
            int r = g * 4 + eq;
            const float* p = &Red[((r * 4 + ei) * 16 + ebg) * 17];
            float a0 = 0.f, a1 = 0.f;
#pragma unroll
            for (int k2 = 0; k2 < 16; k2 += 2) { a0 += p[k2]; a1 += p[k2 + 1]; }
            s[g] = a0 + a1;
        }

        float rg = fsig(xr + s[0] + bR);
        float zg = fsig(xz + s[1] + bZ);
        float ng = tanhf(xn + rg * (s[2] + bN));
        float hnew = (1.0f - zg) * ng + zg * hprev;

        __stcg(&hWrit[ej * 64 + eb], hnew);
        g_HS[(t * B_SZ + eb) * H_SZ + ej] = hnew;

        __syncthreads();   // all h stores done (happens-before tid0's release)
        if (tid == 0)
            asm volatile("red.release.gpu.add.u32 [%0], %1;"
                         :: "l"(arr), "r"(1u) : "memory");
    }

    // --- replay-safe counter reset ---
    if (tid == 0) {
        unsigned target = (unsigned)NCTA2 * (unsigned)T_STEPS;
        unsigned v;
        do {
            asm volatile("ld.acquire.gpu.u32 %0, [%1];"
                         : "=r"(v) : "l"(arr) : "memory");
        } while (v < target);
        if (atomicAdd(&g_cnt, 1u) == (unsigned)(NCTA2 - 1)) {
            atomicExch(&g_cnt, 0u);
            atomicExch(&g_arrive, 0u);
        }
    }
}

// ---------------------------------------------------------------------------
// K3: y[m][o] = sum_j HS[m][j] * w_out[o][j] + b_out[o]   (M=32768, N=16, K=512)
// ---------------------------------------------------------------------------
__global__ void __launch_bounds__(128, 4)
k3_out(const float* __restrict__ wout, const float* __restrict__ bout,
       float* __restrict__ y)
{
    __shared__ float As[32][132];
    __shared__ float Wsh[32][16];

    const int tid = threadIdx.x;
    const int tx = tid & 3;
    const int ty = tid >> 2;
    const int m0 = blockIdx.x * 128;

    float c[4][4];
#pragma unroll
    for (int i = 0; i < 4; i++)
#pragma unroll
        for (int jj = 0; jj < 4; jj++) c[i][jj] = 0.f;

    for (int kc = 0; kc < H_SZ; kc += 32) {
        __syncthreads();
#pragma unroll
        for (int i = 0; i < 8; i++) {
            int lin = tid + i * 128;
            int m = lin >> 3, k4 = lin & 7;
            float4 v = *(const float4*)&g_HS[(m0 + m) * H_SZ + kc + k4 * 4];
            As[k4 * 4 + 0][m] = v.x; As[k4 * 4 + 1][m] = v.y;
            As[k4 * 4 + 2][m] = v.z; As[k4 * 4 + 3][m] = v.w;
        }
#pragma unroll
        for (int i = 0; i < 4; i++) {
            int lin = tid + i * 128;
            int n = lin >> 5, k = lin & 31;
            Wsh[k][n] = wout[n * H_SZ + kc + k];
        }
        __syncthreads();
#pragma unroll
        for (int k = 0; k < 32; k++) {
            float a[4], w[4];
#pragma unroll
            for (int i = 0; i < 4; i++) a[i] = As[k][ty * 4 + i];
#pragma unroll
            for (int jj = 0; jj < 4; jj++) w[jj] = Wsh[k][tx * 4 + jj];
#pragma unroll
            for (int i = 0; i < 4; i++)
#pragma unroll
                for (int jj = 0; jj < 4; jj++)
                    c[i][jj] = fmaf(a[i], w[jj], c[i][jj]);
        }
    }

    float bb[4];
#pragma unroll
    for (int jj = 0; jj < 4; jj++) bb[jj] = __ldg(&bout[tx * 4 + jj]);
#pragma unroll
    for (int i = 0; i < 4; i++) {
        float4 v;
        v.x = c[i][0] + bb[0]; v.y = c[i][1] + bb[1];
        v.z = c[i][2] + bb[2]; v.w = c[i][3] + bb[3];
        *(float4*)&y[(m0 + ty * 4 + i) * O_SZ + tx * 4] = v;
    }
}

// ---------------------------------------------------------------------------
// Entry point
// ---------------------------------------------------------------------------
extern "C" void kernel_launch(void* const* d_in, const int* in_sizes, int n_in,
                              void* d_out, int out_size)
{
    const float* x    = (const float*)d_in[0];   // (T,B,F)
    const float* wih  = (const float*)d_in[1];   // (3H,F)
    const float* whh  = (const float*)d_in[2];   // (3H,H)
    const float* bih  = (const float*)d_in[3];   // (3H)
    const float* bhh  = (const float*)d_in[4];   // (3H)
    const float* wout = (const float*)d_in[5];   // (O,H)
    const float* bout = (const float*)d_in[6];   // (O)
    float* y = (float*)d_out;                    // (T,B,O)

    cudaFuncSetAttribute(k2_gru, cudaFuncAttributeMaxDynamicSharedMemorySize,
                         SMEM2_BYTES);

    // 1) xg = x @ w_ih^T + b_ih
    k1_xg<<<dim3(G_SZ / 64, (T_STEPS * B_SZ) / 64), 256>>>(x, wih, bih);

    // 2) persistent GRU recurrence
    k2_gru<<<NCTA2, NTHR2, SMEM2_BYTES>>>(whh, bhh);

    // 3) output projection
    k3_out<<<(T_STEPS * B_SZ) / 128, 128>>>(wout, bout, y);
}

// round 5
// speedup vs baseline: 2.5914x; 1.0246x over previous
#include <cuda_runtime.h>
#include <cuda_bf16.h>
#include <math.h>
#include <stdint.h>

// Problem constants
#define T_STEPS 512
#define B_SZ    64
#define F_SZ    128
#define H_SZ    512
#define O_SZ    16
#define G_SZ    (3 * H_SZ)   // 1536

// K2 config: 64 CTAs x 384 threads (12 working warps), each CTA owns 8 j-units
#define NCTA2   64
#define NTHR2   384
#define JPC     8
#define NGATE   24           // 8 j * 3 gates

// K2 dynamic SMEM: B fragments + D exchange
#define BFRAG_U32   (2 * 3 * 32 * 32 * 2)     // 12288 u32 = 49152 B
#define DSM_STRIDE  56                         // floats; 224B rows (16B aligned)
#define DSM_FLOATS  (128 * DSM_STRIDE)         // 7168 floats = 28672 B
#define SMEM2_BYTES (BFRAG_U32 * 4 + DSM_FLOATS * 4)   // 77824

// ---------------------------------------------------------------------------
// Device scratch
// ---------------------------------------------------------------------------
__device__ float g_XG[T_STEPS * B_SZ * G_SZ];       // input-side gate preacts
__device__ float g_HS[T_STEPS * B_SZ * H_SZ];       // hidden states (for K3)
// h in HMMA A-fragment layout: [buf][(mt*32 + ks)*128 + lane*4 + reg]
__device__ uint32_t g_Hfrag[2][8 * 32 * 128];
__device__ unsigned g_arrive = 0;
__device__ unsigned g_cnt = 0;

// ---------------------------------------------------------------------------
// Helpers
// ---------------------------------------------------------------------------
__device__ __forceinline__ float fsig(float x) { return 1.0f / (1.0f + __expf(-x)); }

__device__ __forceinline__ uint32_t pkbf(float a, float b) {
    return (uint32_t)__bfloat16_as_ushort(__float2bfloat16(a))
         | ((uint32_t)__bfloat16_as_ushort(__float2bfloat16(b)) << 16);
}

// mma.sync m16n8k16 row.col f32.bf16.bf16.f32 (compute_103-legal, tensor pipe)
__device__ __forceinline__ void hmma(float* d, const uint4& a, uint32_t b0, uint32_t b1) {
    asm volatile(
        "mma.sync.aligned.m16n8k16.row.col.f32.bf16.bf16.f32 "
        "{%0,%1,%2,%3}, {%4,%5,%6,%7}, {%8,%9}, {%0,%1,%2,%3};"
        : "+f"(d[0]), "+f"(d[1]), "+f"(d[2]), "+f"(d[3])
        : "r"(a.x), "r"(a.y), "r"(a.z), "r"(a.w), "r"(b0), "r"(b1));
}

// ---------------------------------------------------------------------------
// K1: xg = x @ w_ih^T + b_ih   (M=32768, N=1536, K=128)
// ---------------------------------------------------------------------------
__global__ void __launch_bounds__(256, 2)
k1_xg(const float* __restrict__ x, const float* __restrict__ wih,
      const float* __restrict__ bih)
{
    __shared__ float As[32][68];
    __shared__ float Bs[32][68];

    const int tid = threadIdx.x;
    const int tx = tid & 15;
    const int ty = tid >> 4;
    const int m0 = blockIdx.y * 64;
    const int n0 = blockIdx.x * 64;

    float c[4][4];
#pragma unroll
    for (int i = 0; i < 4; i++)
#pragma unroll
        for (int j = 0; j < 4; j++) c[i][j] = 0.f;

    for (int kc = 0; kc < F_SZ; kc += 32) {
        __syncthreads();
#pragma unroll
        for (int i = 0; i < 2; i++) {
            int lin = tid + i * 256;
            int m = lin >> 3, k4 = lin & 7;
            float4 v = *(const float4*)&x[(m0 + m) * F_SZ + kc + k4 * 4];
            As[k4 * 4 + 0][m] = v.x; As[k4 * 4 + 1][m] = v.y;
            As[k4 * 4 + 2][m] = v.z; As[k4 * 4 + 3][m] = v.w;
        }
#pragma unroll
        for (int i = 0; i < 2; i++) {
            int lin = tid + i * 256;
            int n = lin >> 3, k4 = lin & 7;
            float4 v = *(const float4*)&wih[(n0 + n) * F_SZ + kc + k4 * 4];
            Bs[k4 * 4 + 0][n] = v.x; Bs[k4 * 4 + 1][n] = v.y;
            Bs[k4 * 4 + 2][n] = v.z; Bs[k4 * 4 + 3][n] = v.w;
        }
        __syncthreads();
#pragma unroll
        for (int k = 0; k < 32; k++) {
            float a[4], b[4];
#pragma unroll
            for (int i = 0; i < 4; i++) a[i] = As[k][ty * 4 + i];
#pragma unroll
            for (int j = 0; j < 4; j++) b[j] = Bs[k][tx * 4 + j];
#pragma unroll
            for (int i = 0; i < 4; i++)
#pragma unroll
                for (int j = 0; j < 4; j++)
                    c[i][j] = fmaf(a[i], b[j], c[i][j]);
        }
    }

    float bb[4];
#pragma unroll
    for (int j = 0; j < 4; j++) bb[j] = __ldg(&bih[n0 + tx * 4 + j]);
#pragma unroll
    for (int i = 0; i < 4; i++) {
        float4 v;
        v.x = c[i][0] + bb[0]; v.y = c[i][1] + bb[1];
        v.z = c[i][2] + bb[2]; v.w = c[i][3] + bb[3];
        *(float4*)&g_XG[(m0 + ty * 4 + i) * G_SZ + n0 + tx * 4] = v;
    }
}

// ---------------------------------------------------------------------------
// K2: persistent HMMA GRU recurrence.
// D[128x48] = [h_hi; h_lo] @ [W_hi | W_lo]^T  (h_lo x W_lo tiles skipped)
// Warp jobs (12): w<8 -> (pass=hi, mt=w); w 8-11 -> (pass=lo, mt=w-8).
// ---------------------------------------------------------------------------
__global__ void __launch_bounds__(NTHR2, 1)
k2_gru(const float* __restrict__ wHH, const float* __restrict__ bHH)
{
    extern __shared__ uint32_t sm[];
    uint32_t* Bsm = sm;                                  // B fragments
    float*    Dsm = (float*)(sm + BFRAG_U32);            // D exchange [128][56]

    const int tid  = threadIdx.x;
    const int wid  = tid >> 5;
    const int lane = tid & 31;
    const int bid  = blockIdx.x;
    const int j0   = bid * JPC;

    // ---- one-time: W -> bf16 hi/lo fragments in SMEM ----
    // entry = (pass, nt, ks, lane): B tile rows k = 16ks.., cols n = nt*8..
    for (int idx = tid; idx < 2 * 3 * 32 * 32; idx += NTHR2) {
        int el   = idx & 31;
        int ks   = (idx >> 5) & 31;
        int nt   = (idx >> 10) % 3;
        int p    = idx / (3 * 1024);
        int n    = nt * 8 + (el >> 2);
        int jl   = n / 3, g = n % 3;
        const float* wr = &wHH[(g * H_SZ + j0 + jl) * H_SZ];
        int k0 = ks * 16 + (el & 3) * 2;
        float w00 = wr[k0], w01 = wr[k0 + 1], w10 = wr[k0 + 8], w11 = wr[k0 + 9];
        if (p) {  // lo parts
            w00 -= __bfloat162float(__float2bfloat16(w00));
            w01 -= __bfloat162float(__float2bfloat16(w01));
            w10 -= __bfloat162float(__float2bfloat16(w10));
            w11 -= __bfloat162float(__float2bfloat16(w11));
        }
        Bsm[idx * 2    ] = pkbf(w00, w01);
        Bsm[idx * 2 + 1] = pkbf(w10, w11);
    }

    // ---- epilogue thread state (threads 0-63: thread == batch b) ----
    float bRr[JPC], bRz[JPC], bRn[JPC], hprev[JPC];
    if (tid < B_SZ) {
#pragma unroll
        for (int jl = 0; jl < JPC; jl++) {
            bRr[jl] = __ldg(&bHH[0 * H_SZ + j0 + jl]);
            bRz[jl] = __ldg(&bHH[1 * H_SZ + j0 + jl]);
            bRn[jl] = __ldg(&bHH[2 * H_SZ + j0 + jl]);
            hprev[jl] = 0.f;
        }
    }
    __syncthreads();

    // producer constants (thread b = tid < 64)
    const int pks   = bid >> 1;            // ks of this CTA's j block
    const int pregb = (bid & 1) << 1;      // reg bit1 from column block
    unsigned* arr = &g_arrive;

    for (int t = 0; t < T_STEPS; t++) {
        // ---- prefetch xg (independent of h) ----
        float xr[JPC], xz[JPC], xn[JPC];
        if (tid < B_SZ) {
            const float* xg = &g_XG[(t * B_SZ + tid) * G_SZ + j0];
            float4 a0 = *(const float4*)&xg[0];
            float4 a1 = *(const float4*)&xg[4];
            float4 b0 = *(const float4*)&xg[H_SZ];
            float4 b1 = *(const float4*)&xg[H_SZ + 4];
            float4 c0 = *(const float4*)&xg[2 * H_SZ];
            float4 c1 = *(const float4*)&xg[2 * H_SZ + 4];
            xr[0]=a0.x; xr[1]=a0.y; xr[2]=a0.z; xr[3]=a0.w;
            xr[4]=a1.x; xr[5]=a1.y; xr[6]=a1.z; xr[7]=a1.w;
            xz[0]=b0.x; xz[1]=b0.y; xz[2]=b0.z; xz[3]=b0.w;
            xz[4]=b1.x; xz[5]=b1.y; xz[6]=b1.z; xz[7]=b1.w;
            xn[0]=c0.x; xn[1]=c0.y; xn[2]=c0.z; xn[3]=c0.w;
            xn[4]=c1.x; xn[5]=c1.y; xn[6]=c1.z; xn[7]=c1.w;
        }

        if (t > 0) {
            // ---- grid barrier: all CTAs committed h(t-1) ----
            if (tid == 0) {
                unsigned target = (unsigned)NCTA2 * (unsigned)t;
                unsigned v;
                do {
                    asm volatile("ld.acquire.gpu.u32 %0, [%1];"
                                 : "=r"(v) : "l"(arr) : "memory");
                } while (v < target);
            }
            __syncthreads();

            // ---- MMA phase (12 working warps) ----
            if (wid < 12) {
                const int pass = wid >> 3;          // 0: W_hi, 1: W_lo
                const int mt   = wid & 7;           // m16 tile (rows mt*16..)
                const uint32_t* hfr =
                    &g_Hfrag[(t + 1) & 1][(mt * 32) * 128 + lane * 4];

                float acc[3][4];
#pragma unroll
                for (int nt = 0; nt < 3; nt++)
#pragma unroll
                    for (int i = 0; i < 4; i++) acc[nt][i] = 0.f;

                uint4 ab[2][8];
#pragma unroll
                for (int kk = 0; kk < 8; kk++)
                    ab[0][kk] = __ldcg((const uint4*)&hfr[kk * 128]);

#pragma unroll
                for (int kb = 0; kb < 4; kb++) {
                    if (kb < 3) {
#pragma unroll
                        for (int kk = 0; kk < 8; kk++)
                            ab[(kb + 1) & 1][kk] =
                                __ldcg((const uint4*)&hfr[((kb + 1) * 8 + kk) * 128]);
                    }
#pragma unroll
                    for (int kk = 0; kk < 8; kk++) {
                        int ks = kb * 8 + kk;
                        uint4 a = ab[kb & 1][kk];
#pragma unroll
                        for (int nt = 0; nt < 3; nt++) {
                            uint2 bb = *(const uint2*)
                                &Bsm[((((pass * 3 + nt) * 32) + ks) * 32 + lane) * 2];
                            hmma(acc[nt], a, bb.x, bb.y);
                        }
                    }
                }

                // store D fragments to SMEM
                const int gid = lane >> 2, tig = lane & 3;
#pragma unroll
                for (int nt = 0; nt < 3; nt++) {
                    int col  = pass * 24 + nt * 8 + tig * 2;
                    int row0 = mt * 16 + gid;
                    *(float2*)&Dsm[row0 * DSM_STRIDE + col] =
                        make_float2(acc[nt][0], acc[nt][1]);
                    *(float2*)&Dsm[(row0 + 8) * DSM_STRIDE + col] =
                        make_float2(acc[nt][2], acc[nt][3]);
                }
            }
            __syncthreads();
        }

        // ---- epilogue: gates + h update (threads 0-63) ----
        if (tid < B_SZ) {
            float s[NGATE];
            if (t > 0) {
                const float* r0 = &Dsm[tid * DSM_STRIDE];          // h_hi rows
                const float* r1 = &Dsm[(tid + 64) * DSM_STRIDE];   // h_lo rows
#pragma unroll
                for (int c4 = 0; c4 < 6; c4++) {
                    float4 p0 = *(const float4*)&r0[c4 * 4];
                    float4 p1 = *(const float4*)&r1[c4 * 4];
                    float4 p2 = *(const float4*)&r0[24 + c4 * 4];
                    s[c4 * 4 + 0] = p0.x + p1.x + p2.x;
                    s[c4 * 4 + 1] = p0.y + p1.y + p2.y;
                    s[c4 * 4 + 2] = p0.z + p1.z + p2.z;
                    s[c4 * 4 + 3] = p0.w + p1.w + p2.w;
                }
            } else {
#pragma unroll
                for (int c = 0; c < NGATE; c++) s[c] = 0.f;
            }

            float hv[JPC];
#pragma unroll
            for (int jl = 0; jl < JPC; jl++) {
                float rr = fsig(xr[jl] + s[jl * 3 + 0] + bRr[jl]);
                float zz = fsig(xz[jl] + s[jl * 3 + 1] + bRz[jl]);
                float nn = tanhf(xn[jl] + rr * (s[jl * 3 + 2] + bRn[jl]));
                hv[jl] = (1.0f - zz) * nn + zz * hprev[jl];
                hprev[jl] = hv[jl];
            }

            // fp32 hidden states for K3
            float* hs = &g_HS[(t * B_SZ + tid) * H_SZ + j0];
            *(float4*)&hs[0] = make_float4(hv[0], hv[1], hv[2], hv[3]);
            *(float4*)&hs[4] = make_float4(hv[4], hv[5], hv[6], hv[7]);

            // h -> bf16 hi/lo fragments (write buffer t&1)
            uint32_t* hw = g_Hfrag[t & 1];
            const int regh = ((tid >> 3) & 1) | pregb;
            const int mth  = tid >> 4;
#pragma unroll
            for (int jl = 0; jl < JPC; jl += 2) {
                float h0 = hv[jl], h1 = hv[jl + 1];
                float l0 = h0 - __bfloat162float(__float2bfloat16(h0));
                float l1 = h1 - __bfloat162float(__float2bfloat16(h1));
                int ln = (tid & 7) * 4 + (jl >> 1);
                hw[((mth       * 32 + pks) * 128) + ln * 4 + regh] = pkbf(h0, h1);
                hw[(((mth + 4) * 32 + pks) * 128) + ln * 4 + regh] = pkbf(l0, l1);
            }
        }

        __syncthreads();   // all h-frag stores done before release
        if (tid == 0)
            asm volatile("red.release.gpu.add.u32 [%0], %1;"
                         :: "l"(arr), "r"(1u) : "memory");
    }

    // ---- replay-safe counter reset ----
    if (tid == 0) {
        unsigned target = (unsigned)NCTA2 * (unsigned)T_STEPS;
        unsigned v;
        do {
            asm volatile("ld.acquire.gpu.u32 %0, [%1];"
                         : "=r"(v) : "l"(arr) : "memory");
        } while (v < target);
        if (atomicAdd(&g_cnt, 1u) == (unsigned)(NCTA2 - 1)) {
            atomicExch(&g_cnt, 0u);
            atomicExch(&g_arrive, 0u);
        }
    }
}

// ---------------------------------------------------------------------------
// K3: y = HS @ w_out^T + b_out   (M=32768, N=16, K=512)
// ---------------------------------------------------------------------------
__global__ void __launch_bounds__(128, 4)
k3_out(const float* __restrict__ wout, const float* __restrict__ bout,
       float* __restrict__ y)
{
    __shared__ float As[32][132];
    __shared__ float Wsh[32][16];

    const int tid = threadIdx.x;
    const int tx = tid & 3;
    const int ty = tid >> 2;
    const int m0 = blockIdx.x * 128;

    float c[4][4];
#pragma unroll
    for (int i = 0; i < 4; i++)
#pragma unroll
        for (int jj = 0; jj < 4; jj++) c[i][jj] = 0.f;

    for (int kc = 0; kc < H_SZ; kc += 32) {
        __syncthreads();
#pragma unroll
        for (int i = 0; i < 8; i++) {
            int lin = tid + i * 128;
            int m = lin >> 3, k4 = lin & 7;
            float4 v = *(const float4*)&g_HS[(m0 + m) * H_SZ + kc + k4 * 4];
            As[k4 * 4 + 0][m] = v.x; As[k4 * 4 + 1][m] = v.y;
            As[k4 * 4 + 2][m] = v.z; As[k4 * 4 + 3][m] = v.w;
        }
#pragma unroll
        for (int i = 0; i < 4; i++) {
            int lin = tid + i * 128;
            int n = lin >> 5, k = lin & 31;
            Wsh[k][n] = wout[n * H_SZ + kc + k];
        }
        __syncthreads();
#pragma unroll
        for (int k = 0; k < 32; k++) {
            float a[4], w[4];
#pragma unroll
            for (int i = 0; i < 4; i++) a[i] = As[k][ty * 4 + i];
#pragma unroll
            for (int jj = 0; jj < 4; jj++) w[jj] = Wsh[k][tx * 4 + jj];
#pragma unroll
            for (int i = 0; i < 4; i++)
#pragma unroll
                for (int jj = 0; jj < 4; jj++)
                    c[i][jj] = fmaf(a[i], w[jj], c[i][jj]);
        }
    }

    float bb[4];
#pragma unroll
    for (int jj = 0; jj < 4; jj++) bb[jj] = __ldg(&bout[tx * 4 + jj]);
#pragma unroll
    for (int i = 0; i < 4; i++) {
        float4 v;
        v.x = c[i][0] + bb[0]; v.y = c[i][1] + bb[1];
        v.z = c[i][2] + bb[2]; v.w = c[i][3] + bb[3];
        *(float4*)&y[(m0 + ty * 4 + i) * O_SZ + tx * 4] = v;
    }
}

// ---------------------------------------------------------------------------
// Entry point
// ---------------------------------------------------------------------------
extern "C" void kernel_launch(void* const* d_in, const int* in_sizes, int n_in,
                              void* d_out, int out_size)
{
    const float* x    = (const float*)d_in[0];   // (T,B,F)
    const float* wih  = (const float*)d_in[1];   // (3H,F)
    const float* whh  = (const float*)d_in[2];   // (3H,H)
    const float* bih  = (const float*)d_in[3];   // (3H)
    const float* bhh  = (const float*)d_in[4];   // (3H)
    const float* wout = (const float*)d_in[5];   // (O,H)
    const float* bout = (const float*)d_in[6];   // (O)
    float* y = (float*)d_out;                    // (T,B,O)

    cudaFuncSetAttribute(k2_gru, cudaFuncAttributeMaxDynamicSharedMemorySize,
                         SMEM2_BYTES);

    // 1) xg = x @ w_ih^T + b_ih
    k1_xg<<<dim3(G_SZ / 64, (T_STEPS * B_SZ) / 64), 256>>>(x, wih, bih);

    // 2) persistent GRU recurrence (HMMA tensor cores)
    k2_gru<<<NCTA2, NTHR2, SMEM2_BYTES>>>(whh, bhh);

    // 3) output projection
    k3_out<<<(T_STEPS * B_SZ) / 128, 128>>>(wout, bout, y);
}

// round 6
// speedup vs baseline: 3.3721x; 1.3013x over previous
#include <cuda_runtime.h>
#include <cuda_bf16.h>
#include <math.h>
#include <stdint.h>

// Problem constants
#define T_STEPS 512
#define B_SZ    64
#define F_SZ    128
#define H_SZ    512
#define O_SZ    16
#define G_SZ    (3 * H_SZ)   // 1536

// K2 config: 128 CTAs x 384 threads, each CTA owns 4 j-units (12 gate cols, pad 16)
#define NCTA2   128
#define NTHR2   384
#define JPC     4
#define NGATE   12

// K2 dynamic SMEM
#define BFRAG_U32   (2 * 2 * 32 * 32 * 2)     // 8192 u32 = 32768 B
#define DSM_STRIDE  36                         // floats (144B rows)
#define DSM_FLOATS  (128 * DSM_STRIDE)         // 4608
#define SMEM2_BYTES (BFRAG_U32 * 4 + DSM_FLOATS * 4)   // 51200

// ---------------------------------------------------------------------------
// Device scratch
// ---------------------------------------------------------------------------
__device__ float g_XG[T_STEPS * B_SZ * G_SZ];       // input-side gate preacts
__device__ float g_HS[T_STEPS * B_SZ * H_SZ];       // hidden states (for K3)
// h in HMMA A-fragment layout: [buf][(mt*32 + ks)*128 + lane*4 + reg]
__device__ uint32_t g_Hfrag[2][8 * 32 * 128];
__device__ unsigned g_arrive = 0;
__device__ unsigned g_cnt = 0;

// ---------------------------------------------------------------------------
// Helpers
// ---------------------------------------------------------------------------
__device__ __forceinline__ float fsig(float x) { return 1.0f / (1.0f + __expf(-x)); }

__device__ __forceinline__ uint32_t pkbf(float a, float b) {
    return (uint32_t)__bfloat16_as_ushort(__float2bfloat16(a))
         | ((uint32_t)__bfloat16_as_ushort(__float2bfloat16(b)) << 16);
}
__device__ __forceinline__ float bflo(float v) {
    return v - __bfloat162float(__float2bfloat16(v));
}

// mma.sync m16n8k16 row.col f32.bf16.bf16.f32
__device__ __forceinline__ void hmma(float* d, const uint4& a, uint32_t b0, uint32_t b1) {
    asm volatile(
        "mma.sync.aligned.m16n8k16.row.col.f32.bf16.bf16.f32 "
        "{%0,%1,%2,%3}, {%4,%5,%6,%7}, {%8,%9}, {%0,%1,%2,%3};"
        : "+f"(d[0]), "+f"(d[1]), "+f"(d[2]), "+f"(d[3])
        : "r"(a.x), "r"(a.y), "r"(a.z), "r"(a.w), "r"(b0), "r"(b1));
}

// ---------------------------------------------------------------------------
// K1: xg = x @ w_ih^T + b_ih  via HMMA split-bf16 (3 products).
// CTA: 256 thr (8 warps), tile M=128 (mt=wid), N=64, K=128.
// ---------------------------------------------------------------------------
__global__ void __launch_bounds__(256, 2)
k1_xg(const float* __restrict__ x, const float* __restrict__ wih,
      const float* __restrict__ bih)
{
    // Bf[part][nt][ks][lane][reg]
    __shared__ uint32_t Bf[2][8][8][32][2];

    const int tid  = threadIdx.x;
    const int wid  = tid >> 5;
    const int lane = tid & 31;
    const int m0 = blockIdx.y * 128;
    const int n0 = blockIdx.x * 64;

    // Build W fragments (hi + lo)
    for (int idx = tid; idx < 2 * 8 * 8 * 32; idx += 256) {
        int el = idx & 31;
        int ks = (idx >> 5) & 7;
        int nt = (idx >> 8) & 7;
        int p  = idx >> 11;
        const float* wr = &wih[(n0 + nt * 8 + (el >> 2)) * F_SZ + ks * 16 + (el & 3) * 2];
        float w00 = wr[0], w01 = wr[1], w10 = wr[8], w11 = wr[9];
        if (p) { w00 = bflo(w00); w01 = bflo(w01); w10 = bflo(w10); w11 = bflo(w11); }
        Bf[p][nt][ks][el][0] = pkbf(w00, w01);
        Bf[p][nt][ks][el][1] = pkbf(w10, w11);
    }
    __syncthreads();

    const int mt  = wid;
    const int gid = lane >> 2;
    const int tig = lane & 3;
    const float* xr0 = &x[(m0 + mt * 16 + gid) * F_SZ];
    const float* xr1 = xr0 + 8 * F_SZ;

    float acc[8][4];
#pragma unroll
    for (int nt = 0; nt < 8; nt++)
#pragma unroll
        for (int i = 0; i < 4; i++) acc[nt][i] = 0.f;

#pragma unroll
    for (int ks = 0; ks < 8; ks++) {
        int kc = ks * 16 + tig * 2;
        float2 x00 = *(const float2*)&xr0[kc];
        float2 x10 = *(const float2*)&xr1[kc];
        float2 x01 = *(const float2*)&xr0[kc + 8];
        float2 x11 = *(const float2*)&xr1[kc + 8];
        uint4 ahi = make_uint4(pkbf(x00.x, x00.y), pkbf(x10.x, x10.y),
                               pkbf(x01.x, x01.y), pkbf(x11.x, x11.y));
        uint4 alo = make_uint4(pkbf(bflo(x00.x), bflo(x00.y)),
                               pkbf(bflo(x10.x), bflo(x10.y)),
                               pkbf(bflo(x01.x), bflo(x01.y)),
                               pkbf(bflo(x11.x), bflo(x11.y)));
#pragma unroll
        for (int nt = 0; nt < 8; nt++) {
            uint2 bh = *(const uint2*)&Bf[0][nt][ks][lane][0];
            uint2 bl = *(const uint2*)&Bf[1][nt][ks][lane][0];
            hmma(acc[nt], ahi, bh.x, bh.y);
            hmma(acc[nt], alo, bh.x, bh.y);
            hmma(acc[nt], ahi, bl.x, bl.y);
        }
    }

    const int row0 = m0 + mt * 16 + gid;
#pragma unroll
    for (int nt = 0; nt < 8; nt++) {
        int col = n0 + nt * 8 + tig * 2;
        float2 bb = *(const float2*)&bih[col];
        *(float2*)&g_XG[row0 * G_SZ + col] =
            make_float2(acc[nt][0] + bb.x, acc[nt][1] + bb.y);
        *(float2*)&g_XG[(row0 + 8) * G_SZ + col] =
            make_float2(acc[nt][2] + bb.x, acc[nt][3] + bb.y);
    }
}

// ---------------------------------------------------------------------------
// K2: persistent HMMA GRU recurrence (128 CTAs).
// D[128x32] = [h_hi; h_lo] @ [W_hi | W_lo]^T  (h_lo x W_lo tiles skipped)
// 12 warps: w<8 -> (pass=hi, mt=w); w 8-11 -> (pass=lo, mt=w-8).
// ---------------------------------------------------------------------------
__global__ void __launch_bounds__(NTHR2, 1)
k2_gru(const float* __restrict__ wHH, const float* __restrict__ bHH)
{
    extern __shared__ uint32_t sm[];
    uint32_t* Bsm = sm;                                  // B fragments
    float*    Dsm = (float*)(sm + BFRAG_U32);            // D exchange [128][36]

    const int tid  = threadIdx.x;
    const int wid  = tid >> 5;
    const int lane = tid & 31;
    const int bid  = blockIdx.x;
    const int j0   = bid * JPC;

    // ---- one-time: W -> bf16 hi/lo fragments in SMEM ----
    for (int idx = tid; idx < 2 * 2 * 32 * 32; idx += NTHR2) {
        int el = idx & 31;
        int ks = (idx >> 5) & 31;
        int nt = (idx >> 10) & 1;
        int p  = idx >> 11;
        int n  = nt * 8 + (el >> 2);
        uint32_t r0 = 0, r1 = 0;
        if (n < NGATE) {
            int jl = n / 3, g = n % 3;
            const float* wr = &wHH[(g * H_SZ + j0 + jl) * H_SZ + ks * 16 + (el & 3) * 2];
            float w00 = wr[0], w01 = wr[1], w10 = wr[8], w11 = wr[9];
            if (p) { w00 = bflo(w00); w01 = bflo(w01); w10 = bflo(w10); w11 = bflo(w11); }
            r0 = pkbf(w00, w01);
            r1 = pkbf(w10, w11);
        }
        int base = (((p * 2 + nt) * 32) + ks) * 32 + el;
        Bsm[base * 2    ] = r0;
        Bsm[base * 2 + 1] = r1;
    }

    // ---- epilogue thread state (threads 0-63: thread == batch b) ----
    float bRr[JPC], bRz[JPC], bRn[JPC], hprev[JPC];
    if (tid < B_SZ) {
#pragma unroll
        for (int jl = 0; jl < JPC; jl++) {
            bRr[jl] = __ldg(&bHH[0 * H_SZ + j0 + jl]);
            bRz[jl] = __ldg(&bHH[1 * H_SZ + j0 + jl]);
            bRn[jl] = __ldg(&bHH[2 * H_SZ + j0 + jl]);
            hprev[jl] = 0.f;
        }
    }
    __syncthreads();

    const int pks = bid >> 2;              // k16 chunk owned by this CTA
    unsigned* arr = &g_arrive;

    for (int t = 0; t < T_STEPS; t++) {
        // ---- prefetch xg (independent of h) ----
        float xr[JPC], xz[JPC], xn[JPC];
        if (tid < B_SZ) {
            const float* xg = &g_XG[(t * B_SZ + tid) * G_SZ + j0];
            float4 a0 = *(const float4*)&xg[0];
            float4 b0 = *(const float4*)&xg[H_SZ];
            float4 c0 = *(const float4*)&xg[2 * H_SZ];
            xr[0]=a0.x; xr[1]=a0.y; xr[2]=a0.z; xr[3]=a0.w;
            xz[0]=b0.x; xz[1]=b0.y; xz[2]=b0.z; xz[3]=b0.w;
            xn[0]=c0.x; xn[1]=c0.y; xn[2]=c0.z; xn[3]=c0.w;
        }

        if (t > 0) {
            // ---- grid barrier ----
            if (tid == 0) {
                unsigned target = (unsigned)NCTA2 * (unsigned)t;
                unsigned v;
                do {
                    asm volatile("ld.acquire.gpu.u32 %0, [%1];"
                                 : "=r"(v) : "l"(arr) : "memory");
                } while (v < target);
            }
            __syncthreads();

            // ---- MMA phase (12 working warps) ----
            if (wid < 12) {
                const int pass = wid >> 3;          // 0: W_hi, 1: W_lo
                const int mt   = wid & 7;
                const uint32_t* hfr =
                    &g_Hfrag[(t + 1) & 1][(mt * 32) * 128 + lane * 4];

                float acc[2][4];
#pragma unroll
                for (int nt = 0; nt < 2; nt++)
#pragma unroll
                    for (int i = 0; i < 4; i++) acc[nt][i] = 0.f;

                uint4 ab[2][8];
#pragma unroll
                for (int kk = 0; kk < 8; kk++)
                    ab[0][kk] = __ldcg((const uint4*)&hfr[kk * 128]);

#pragma unroll
                for (int kb = 0; kb < 4; kb++) {
                    if (kb < 3) {
#pragma unroll
                        for (int kk = 0; kk < 8; kk++)
                            ab[(kb + 1) & 1][kk] =
                                __ldcg((const uint4*)&hfr[((kb + 1) * 8 + kk) * 128]);
                    }
#pragma unroll
                    for (int kk = 0; kk < 8; kk++) {
                        int ks = kb * 8 + kk;
                        uint4 a = ab[kb & 1][kk];
#pragma unroll
                        for (int nt = 0; nt < 2; nt++) {
                            uint2 bb = *(const uint2*)
                                &Bsm[((((pass * 2 + nt) * 32) + ks) * 32 + lane) * 2];
                            hmma(acc[nt], a, bb.x, bb.y);
                        }
                    }
                }

                const int gid = lane >> 2, tig = lane & 3;
#pragma unroll
                for (int nt = 0; nt < 2; nt++) {
                    int col  = pass * 16 + nt * 8 + tig * 2;
                    int row0 = mt * 16 + gid;
                    *(float2*)&Dsm[row0 * DSM_STRIDE + col] =
                        make_float2(acc[nt][0], acc[nt][1]);
                    *(float2*)&Dsm[(row0 + 8) * DSM_STRIDE + col] =
                        make_float2(acc[nt][2], acc[nt][3]);
                }
            }
            __syncthreads();
        }

        // ---- epilogue: gates + h update (threads 0-63) ----
        if (tid < B_SZ) {
            float s[NGATE];
            if (t > 0) {
                const float* r0 = &Dsm[tid * DSM_STRIDE];          // h_hi rows
                const float* r1 = &Dsm[(tid + 64) * DSM_STRIDE];   // h_lo rows
#pragma unroll
                for (int c4 = 0; c4 < 3; c4++) {
                    float4 p0 = *(const float4*)&r0[c4 * 4];
                    float4 p1 = *(const float4*)&r1[c4 * 4];
                    float4 p2 = *(const float4*)&r0[16 + c4 * 4];
                    s[c4 * 4 + 0] = p0.x + p1.x + p2.x;
                    s[c4 * 4 + 1] = p0.y + p1.y + p2.y;
                    s[c4 * 4 + 2] = p0.z + p1.z + p2.z;
                    s[c4 * 4 + 3] = p0.w + p1.w + p2.w;
                }
            } else {
#pragma unroll
                for (int c = 0; c < NGATE; c++) s[c] = 0.f;
            }

            float hv[JPC];
#pragma unroll
            for (int jl = 0; jl < JPC; jl++) {
                float rr = fsig(xr[jl] + s[jl * 3 + 0] + bRr[jl]);
                float zz = fsig(xz[jl] + s[jl * 3 + 1] + bRz[jl]);
                float nn = tanhf(xn[jl] + rr * (s[jl * 3 + 2] + bRn[jl]));
                hv[jl] = (1.0f - zz) * nn + zz * hprev[jl];
                hprev[jl] = hv[jl];
            }

            // fp32 hidden states for K3
            *(float4*)&g_HS[(t * B_SZ + tid) * H_SZ + j0] =
                make_float4(hv[0], hv[1], hv[2], hv[3]);

            // h -> bf16 hi/lo fragments (write buffer t&1)
            uint32_t* hw = g_Hfrag[t & 1];
            const int mth = tid >> 4;
#pragma unroll
            for (int jlp = 0; jlp < JPC; jlp += 2) {
                int cc   = (bid & 3) * 2 + (jlp >> 1);       // col pair idx in k16
                int ln   = (tid & 7) * 4 + (cc & 3);
                int reg  = ((tid >> 3) & 1) | ((cc >> 2) << 1);
                float h0 = hv[jlp], h1 = hv[jlp + 1];
                hw[((mth       * 32 + pks) * 128) + ln * 4 + reg] = pkbf(h0, h1);
                hw[(((mth + 4) * 32 + pks) * 128) + ln * 4 + reg] =
                    pkbf(bflo(h0), bflo(h1));
            }
        }

        __syncthreads();   // all h-frag stores done before release
        if (tid == 0)
            asm volatile("red.release.gpu.add.u32 [%0], %1;"
                         :: "l"(arr), "r"(1u) : "memory");
    }

    // ---- replay-safe counter reset ----
    if (tid == 0) {
        unsigned target = (unsigned)NCTA2 * (unsigned)T_STEPS;
        unsigned v;
        do {
            asm volatile("ld.acquire.gpu.u32 %0, [%1];"
                         : "=r"(v) : "l"(arr) : "memory");
        } while (v < target);
        if (atomicAdd(&g_cnt, 1u) == (unsigned)(NCTA2 - 1)) {
            atomicExch(&g_cnt, 0u);
            atomicExch(&g_arrive, 0u);
        }
    }
}

// ---------------------------------------------------------------------------
// K3: y = HS @ w_out^T + b_out   (M=32768, N=16, K=512)
// ---------------------------------------------------------------------------
__global__ void __launch_bounds__(128, 4)
k3_out(const float* __restrict__ wout, const float* __restrict__ bout,
       float* __restrict__ y)
{
    __shared__ float As[32][132];
    __shared__ float Wsh[32][16];

    const int tid = threadIdx.x;
    const int tx = tid & 3;
    const int ty = tid >> 2;
    const int m0 = blockIdx.x * 128;

    float c[4][4];
#pragma unroll
    for (int i = 0; i < 4; i++)
#pragma unroll
        for (int jj = 0; jj < 4; jj++) c[i][jj] = 0.f;

    for (int kc = 0; kc < H_SZ; kc += 32) {
        __syncthreads();
#pragma unroll
        for (int i = 0; i < 8; i++) {
            int lin = tid + i * 128;
            int m = lin >> 3, k4 = lin & 7;
            float4 v = *(const float4*)&g_HS[(m0 + m) * H_SZ + kc + k4 * 4];
            As[k4 * 4 + 0][m] = v.x; As[k4 * 4 + 1][m] = v.y;
            As[k4 * 4 + 2][m] = v.z; As[k4 * 4 + 3][m] = v.w;
        }
#pragma unroll
        for (int i = 0; i < 4; i++) {
            int lin = tid + i * 128;
            int n = lin >> 5, k = lin & 31;
            Wsh[k][n] = wout[n * H_SZ + kc + k];
        }
        __syncthreads();
#pragma unroll
        for (int k = 0; k < 32; k++) {
            float a[4], w[4];
#pragma unroll
            for (int i = 0; i < 4; i++) a[i] = As[k][ty * 4 + i];
#pragma unroll
            for (int jj = 0; jj < 4; jj++) w[jj] = Wsh[k][tx * 4 + jj];
#pragma unroll
            for (int i = 0; i < 4; i++)
#pragma unroll
                for (int jj = 0; jj < 4; jj++)
                    c[i][jj] = fmaf(a[i], w[jj], c[i][jj]);
        }
    }

    float bb[4];
#pragma unroll
    for (int jj = 0; jj < 4; jj++) bb[jj] = __ldg(&bout[tx * 4 + jj]);
#pragma unroll
    for (int i = 0; i < 4; i++) {
        float4 v;
        v.x = c[i][0] + bb[0]; v.y = c[i][1] + bb[1];
        v.z = c[i][2] + bb[2]; v.w = c[i][3] + bb[3];
        *(float4*)&y[(m0 + ty * 4 + i) * O_SZ + tx * 4] = v;
    }
}

// ---------------------------------------------------------------------------
// Entry point
// ---------------------------------------------------------------------------
extern "C" void kernel_launch(void* const* d_in, const int* in_sizes, int n_in,
                              void* d_out, int out_size)
{
    const float* x    = (const float*)d_in[0];   // (T,B,F)
    const float* wih  = (const float*)d_in[1];   // (3H,F)
    const float* whh  = (const float*)d_in[2];   // (3H,H)
    const float* bih  = (const float*)d_in[3];   // (3H)
    const float* bhh  = (const float*)d_in[4];   // (3H)
    const float* wout = (const float*)d_in[5];   // (O,H)
    const float* bout = (const float*)d_in[6];   // (O)
    float* y = (float*)d_out;                    // (T,B,O)

    cudaFuncSetAttribute(k2_gru, cudaFuncAttributeMaxDynamicSharedMemorySize,
                         SMEM2_BYTES);

    // 1) xg = x @ w_ih^T + b_ih  (HMMA split-bf16)
    k1_xg<<<dim3(G_SZ / 64, (T_STEPS * B_SZ) / 128), 256>>>(x, wih, bih);

    // 2) persistent GRU recurrence (HMMA, 128 CTAs)
    k2_gru<<<NCTA2, NTHR2, SMEM2_BYTES>>>(whh, bhh);

    // 3) output projection
    k3_out<<<(T_STEPS * B_SZ) / 128, 128>>>(wout, bout, y);
}

// round 7
// speedup vs baseline: 4.2443x; 1.2586x over previous
#include <cuda_runtime.h>
#include <cuda_bf16.h>
#include <math.h>
#include <stdint.h>

// Problem constants
#define T_STEPS 512
#define B_SZ    64
#define F_SZ    128
#define H_SZ    512
#define O_SZ    16
#define G_SZ    (3 * H_SZ)   // 1536

// K2 config: 128 CTAs = 2 batch-groups x 64 j-blocks; CTA = 32 batches x 8 j
#define NCTA2   128
#define NTHR2   256
#define JPC     8
#define NG      24            // 8 j * 3 gates (3 full n8 tiles, no padding)
#define GRPCTA  64            // CTAs per batch-group

// K2 dynamic SMEM
#define BSM_U32     (2 * 3 * 32 * 32 * 2)   // 12288 u32 = 49152 B
#define DST         26                       // Dsm row stride (floats)
#define DSM_FLOATS  (6 * 32 * DST)           // 4992
#define SMEM2_BYTES (BSM_U32 * 4 + DSM_FLOATS * 4)   // 69120

// ---------------------------------------------------------------------------
// Device scratch
// ---------------------------------------------------------------------------
__device__ float g_XG[T_STEPS * B_SZ * G_SZ];       // input-side gate preacts
__device__ float g_HS[T_STEPS * B_SZ * H_SZ];       // hidden states (for K3)
// h in HMMA A-fragment layout: [buf][(mt*32 + ks)*128 + lane*4 + reg]
__device__ uint32_t g_Hfrag[2][8 * 32 * 128];
__device__ __align__(128) unsigned g_arr2[2][32];   // per-group arrival counters
__device__ __align__(128) unsigned g_cnt2[2][32];   // per-group reset counters

// ---------------------------------------------------------------------------
// Helpers
// ---------------------------------------------------------------------------
__device__ __forceinline__ float fsig(float x) { return 1.0f / (1.0f + __expf(-x)); }
__device__ __forceinline__ float ftanh(float x) { return 2.0f / (1.0f + __expf(-2.0f * x)) - 1.0f; }

__device__ __forceinline__ uint32_t pkbf(float a, float b) {
    return (uint32_t)__bfloat16_as_ushort(__float2bfloat16(a))
         | ((uint32_t)__bfloat16_as_ushort(__float2bfloat16(b)) << 16);
}
__device__ __forceinline__ float bflo(float v) {
    return v - __bfloat162float(__float2bfloat16(v));
}

// mma.sync m16n8k16 row.col f32.bf16.bf16.f32
__device__ __forceinline__ void hmma(float* d, const uint4& a, uint32_t b0, uint32_t b1) {
    asm volatile(
        "mma.sync.aligned.m16n8k16.row.col.f32.bf16.bf16.f32 "
        "{%0,%1,%2,%3}, {%4,%5,%6,%7}, {%8,%9}, {%0,%1,%2,%3};"
        : "+f"(d[0]), "+f"(d[1]), "+f"(d[2]), "+f"(d[3])
        : "r"(a.x), "r"(a.y), "r"(a.z), "r"(a.w), "r"(b0), "r"(b1));
}

// ---------------------------------------------------------------------------
// K1: xg = x @ w_ih^T + b_ih  via HMMA split-bf16 (3 products).
// ---------------------------------------------------------------------------
__global__ void __launch_bounds__(256, 2)
k1_xg(const float* __restrict__ x, const float* __restrict__ wih,
      const float* __restrict__ bih)
{
    __shared__ uint32_t Bf[2][8][8][32][2];

    const int tid  = threadIdx.x;
    const int wid  = tid >> 5;
    const int lane = tid & 31;
    const int m0 = blockIdx.y * 128;
    const int n0 = blockIdx.x * 64;

    for (int idx = tid; idx < 2 * 8 * 8 * 32; idx += 256) {
        int el = idx & 31;
        int ks = (idx >> 5) & 7;
        int nt = (idx >> 8) & 7;
        int p  = idx >> 11;
        const float* wr = &wih[(n0 + nt * 8 + (el >> 2)) * F_SZ + ks * 16 + (el & 3) * 2];
        float w00 = wr[0], w01 = wr[1], w10 = wr[8], w11 = wr[9];
        if (p) { w00 = bflo(w00); w01 = bflo(w01); w10 = bflo(w10); w11 = bflo(w11); }
        Bf[p][nt][ks][el][0] = pkbf(w00, w01);
        Bf[p][nt][ks][el][1] = pkbf(w10, w11);
    }
    __syncthreads();

    const int mt  = wid;
    const int gid = lane >> 2;
    const int tig = lane & 3;
    const float* xr0 = &x[(m0 + mt * 16 + gid) * F_SZ];
    const float* xr1 = xr0 + 8 * F_SZ;

    float acc[8][4];
#pragma unroll
    for (int nt = 0; nt < 8; nt++)
#pragma unroll
        for (int i = 0; i < 4; i++) acc[nt][i] = 0.f;

#pragma unroll
    for (int ks = 0; ks < 8; ks++) {
        int kc = ks * 16 + tig * 2;
        float2 x00 = *(const float2*)&xr0[kc];
        float2 x10 = *(const float2*)&xr1[kc];
        float2 x01 = *(const float2*)&xr0[kc + 8];
        float2 x11 = *(const float2*)&xr1[kc + 8];
        uint4 ahi = make_uint4(pkbf(x00.x, x00.y), pkbf(x10.x, x10.y),
                               pkbf(x01.x, x01.y), pkbf(x11.x, x11.y));
        uint4 alo = make_uint4(pkbf(bflo(x00.x), bflo(x00.y)),
                               pkbf(bflo(x10.x), bflo(x10.y)),
                               pkbf(bflo(x01.x), bflo(x01.y)),
                               pkbf(bflo(x11.x), bflo(x11.y)));
#pragma unroll
        for (int nt = 0; nt < 8; nt++) {
            uint2 bh = *(const uint2*)&Bf[0][nt][ks][lane][0];
            uint2 bl = *(const uint2*)&Bf[1][nt][ks][lane][0];
            hmma(acc[nt], ahi, bh.x, bh.y);
            hmma(acc[nt], alo, bh.x, bh.y);
            hmma(acc[nt], ahi, bl.x, bl.y);
        }
    }

    const int row0 = m0 + mt * 16 + gid;
#pragma unroll
    for (int nt = 0; nt < 8; nt++) {
        int col = n0 + nt * 8 + tig * 2;
        float2 bb = *(const float2*)&bih[col];
        *(float2*)&g_XG[row0 * G_SZ + col] =
            make_float2(acc[nt][0] + bb.x, acc[nt][1] + bb.y);
        *(float2*)&g_XG[(row0 + 8) * G_SZ + col] =
            make_float2(acc[nt][2] + bb.x, acc[nt][3] + bb.y);
    }
}

// ---------------------------------------------------------------------------
// K2: persistent HMMA GRU recurrence, 2-D tiled (32 batches x 8 j per CTA).
// Warps 0-3 ("hi"): A rows = own-batch h_hi, both W passes (hi, lo).
// Warps 4-7 ("lo"): A rows = own-batch h_lo, W_hi pass only.
// kh = warp&1 splits K (16 ks each). 144 HMMA/SMSP, 64KB L2 reads/CTA/step.
// ---------------------------------------------------------------------------
__global__ void __launch_bounds__(NTHR2, 1)
k2_gru(const float* __restrict__ wHH, const float* __restrict__ bHH)
{
    extern __shared__ uint32_t sm[];
    uint32_t* Bsm = sm;
    float*    Dsm = (float*)(sm + BSM_U32);

    const int tid  = threadIdx.x;
    const int wid  = tid >> 5;
    const int lane = tid & 31;
    const int bid  = blockIdx.x;
    const int grp  = bid & 1;
    const int b0   = grp * 32;
    const int j0   = (bid >> 1) * JPC;

    // ---- one-time: W -> bf16 hi/lo fragments in SMEM (24 real cols) ----
    for (int idx = tid; idx < 2 * 3 * 32 * 32; idx += NTHR2) {
        int el = idx & 31;
        int ks = (idx >> 5) & 31;
        int nt = (idx >> 10) % 3;
        int p  = idx / (3 * 1024);
        int n  = nt * 8 + (el >> 2);
        int jl = n / 3, g = n % 3;
        const float* wr = &wHH[(g * H_SZ + j0 + jl) * H_SZ + ks * 16 + (el & 3) * 2];
        float w00 = wr[0], w01 = wr[1], w10 = wr[8], w11 = wr[9];
        if (p) { w00 = bflo(w00); w01 = bflo(w01); w10 = bflo(w10); w11 = bflo(w11); }
        int base = ((((p * 3 + nt) * 32) + ks) * 32 + el) * 2;
        Bsm[base    ] = pkbf(w00, w01);
        Bsm[base + 1] = pkbf(w10, w11);
    }

    // ---- epilogue state: thread = (batch eb, j-local jl) ----
    const int eb = tid >> 3;
    const int jl = tid & 7;
    const float bR = __ldg(&bHH[0 * H_SZ + j0 + jl]);
    const float bZ = __ldg(&bHH[1 * H_SZ + j0 + jl]);
    const float bN = __ldg(&bHH[2 * H_SZ + j0 + jl]);
    float hprev = 0.f;
    __syncthreads();

    // ---- MMA warp constants ----
    const int isHi = (wid < 4);
    const int mtl  = (wid >> 1) & 1;
    const int kh   = wid & 1;
    const int mtg  = (isHi ? 0 : 4) + (b0 >> 4) + mtl;
    const int gid  = lane >> 2;
    const int tig  = lane & 3;

    unsigned* arr = &g_arr2[grp][0];

    for (int t = 0; t < T_STEPS; t++) {
        // prefetch xg (independent of h)
        const int gbase = (t * B_SZ + b0 + eb) * G_SZ + j0 + jl;
        float xr = __ldg(&g_XG[gbase]);
        float xz = __ldg(&g_XG[gbase + H_SZ]);
        float xn = __ldg(&g_XG[gbase + 2 * H_SZ]);

        if (t > 0) {
            // ---- group barrier: all 64 CTAs of this batch-half committed ----
            if (tid == 0) {
                unsigned target = (unsigned)GRPCTA * (unsigned)t;
                unsigned v;
                do {
                    asm volatile("ld.acquire.gpu.u32 %0, [%1];"
                                 : "=r"(v) : "l"(arr) : "memory");
                } while (v < target);
            }
            __syncthreads();

            // ---- MMA phase ----
            const uint32_t* hfr =
                &g_Hfrag[(t + 1) & 1][(mtg * 32 + kh * 16) * 128 + lane * 4];

            float acc[2][3][4];
#pragma unroll
            for (int p = 0; p < 2; p++)
#pragma unroll
                for (int nt = 0; nt < 3; nt++)
#pragma unroll
                    for (int i = 0; i < 4; i++) acc[p][nt][i] = 0.f;

            uint4 ab[16];
#pragma unroll
            for (int p = 0; p < 16; p++)
                ab[p] = __ldcg((const uint4*)&hfr[p * 128]);

#pragma unroll
            for (int kk = 0; kk < 16; kk++) {
                int ks = kh * 16 + kk;
#pragma unroll
                for (int nt = 0; nt < 3; nt++) {
                    uint2 bb = *(const uint2*)&Bsm[((nt * 32 + ks) * 32 + lane) * 2];
                    hmma(acc[0][nt], ab[kk], bb.x, bb.y);
                }
                if (isHi) {
#pragma unroll
                    for (int nt = 0; nt < 3; nt++) {
                        uint2 bb = *(const uint2*)
                            &Bsm[(((3 + nt) * 32 + ks) * 32 + lane) * 2];
                        hmma(acc[1][nt], ab[kk], bb.x, bb.y);
                    }
                }
            }

            // ---- store D partials ----
            const int npass = isHi ? 2 : 1;
#pragma unroll
            for (int p = 0; p < 2; p++) {
                if (p >= npass) break;
                int slot = isHi ? (p * 2 + kh) : (4 + kh);
#pragma unroll
                for (int nt = 0; nt < 3; nt++) {
                    int col = nt * 8 + tig * 2;
                    int lb  = mtl * 16 + gid;
                    *(float2*)&Dsm[(slot * 32 + lb) * DST + col] =
                        make_float2(acc[p][nt][0], acc[p][nt][1]);
                    *(float2*)&Dsm[(slot * 32 + lb + 8) * DST + col] =
                        make_float2(acc[p][nt][2], acc[p][nt][3]);
                }
            }
            __syncthreads();
        }

        // ---- epilogue: all 256 threads, one (b, j) each ----
        float s0 = 0.f, s1 = 0.f, s2 = 0.f;
        if (t > 0) {
#pragma unroll
            for (int sl = 0; sl < 6; sl++) {
                const float* pr = &Dsm[(sl * 32 + eb) * DST + jl * 3];
                s0 += pr[0]; s1 += pr[1]; s2 += pr[2];
            }
        }

        float rr = fsig(xr + s0 + bR);
        float zz = fsig(xz + s1 + bZ);
        float nn = ftanh(xn + rr * (s2 + bN));
        float hnew = (1.0f - zz) * nn + zz * hprev;
        hprev = hnew;

        g_HS[(t * B_SZ + b0 + eb) * H_SZ + j0 + jl] = hnew;

        float hlo = bflo(hnew);
        float hn1 = __shfl_down_sync(0xffffffffu, hnew, 1);
        float hl1 = __shfl_down_sync(0xffffffffu, hlo, 1);
        if (!(jl & 1)) {
            uint32_t* hw = g_Hfrag[t & 1];
            int r   = b0 + eb;
            int c   = j0 + jl;
            int ks  = c >> 4;
            int lnw = (r & 7) * 4 + ((c >> 1) & 3);
            int reg = (((c >> 3) & 1) << 1) | ((r >> 3) & 1);
            hw[((r >> 4) * 32 + ks) * 128 + lnw * 4 + reg]       = pkbf(hnew, hn1);
            hw[(((r >> 4) + 4) * 32 + ks) * 128 + lnw * 4 + reg] = pkbf(hlo, hl1);
        }

        __syncthreads();   // all h-frag stores done before release
        if (tid == 0)
            asm volatile("red.release.gpu.add.u32 [%0], %1;"
                         :: "l"(arr), "r"(1u) : "memory");
    }

    // ---- replay-safe per-group counter reset ----
    if (tid == 0) {
        unsigned target = (unsigned)GRPCTA * (unsigned)T_STEPS;
        unsigned v;
        do {
            asm volatile("ld.acquire.gpu.u32 %0, [%1];"
                         : "=r"(v) : "l"(arr) : "memory");
        } while (v < target);
        if (atomicAdd(&g_cnt2[grp][0], 1u) == (unsigned)(GRPCTA - 1)) {
            atomicExch(&g_cnt2[grp][0], 0u);
            atomicExch(&g_arr2[grp][0], 0u);
        }
    }
}

// ---------------------------------------------------------------------------
// K3: y = HS @ w_out^T + b_out   (M=32768, N=16, K=512)
// ---------------------------------------------------------------------------
__global__ void __launch_bounds__(128, 4)
k3_out(const float* __restrict__ wout, const float* __restrict__ bout,
       float* __restrict__ y)
{
    __shared__ float As[32][132];
    __shared__ float Wsh[32][16];

    const int tid = threadIdx.x;
    const int tx = tid & 3;
    const int ty = tid >> 2;
    const int m0 = blockIdx.x * 128;

    float c[4][4];
#pragma unroll
    for (int i = 0; i < 4; i++)
#pragma unroll
        for (int jj = 0; jj < 4; jj++) c[i][jj] = 0.f;

    for (int kc = 0; kc < H_SZ; kc += 32) {
        __syncthreads();
#pragma unroll
        for (int i = 0; i < 8; i++) {
            int lin = tid + i * 128;
            int m = lin >> 3, k4 = lin & 7;
            float4 v = *(const float4*)&g_HS[(m0 + m) * H_SZ + kc + k4 * 4];
            As[k4 * 4 + 0][m] = v.x; As[k4 * 4 + 1][m] = v.y;
            As[k4 * 4 + 2][m] = v.z; As[k4 * 4 + 3][m] = v.w;
        }
#pragma unroll
        for (int i = 0; i < 4; i++) {
            int lin = tid + i * 128;
            int n = lin >> 5, k = lin & 31;
            Wsh[k][n] = wout[n * H_SZ + kc + k];
        }
        __syncthreads();
#pragma unroll
        for (int k = 0; k < 32; k++) {
            float a[4], w[4];
#pragma unroll
            for (int i = 0; i < 4; i++) a[i] = As[k][ty * 4 + i];
#pragma unroll
            for (int jj = 0; jj < 4; jj++) w[jj] = Wsh[k][tx * 4 + jj];
#pragma unroll
            for (int i = 0; i < 4; i++)
#pragma unroll
                for (int jj = 0; jj < 4; jj++)
                    c[i][jj] = fmaf(a[i], w[jj], c[i][jj]);
        }
    }

    float bb[4];
#pragma unroll
    for (int jj = 0; jj < 4; jj++) bb[jj] = __ldg(&bout[tx * 4 + jj]);
#pragma unroll
    for (int i = 0; i < 4; i++) {
        float4 v;
        v.x = c[i][0] + bb[0]; v.y = c[i][1] + bb[1];
        v.z = c[i][2] + bb[2]; v.w = c[i][3] + bb[3];
        *(float4*)&y[(m0 + ty * 4 + i) * O_SZ + tx * 4] = v;
    }
}

// ---------------------------------------------------------------------------
// Entry point
// ---------------------------------------------------------------------------
extern "C" void kernel_launch(void* const* d_in, const int* in_sizes, int n_in,
                              void* d_out, int out_size)
{
    const float* x    = (const float*)d_in[0];   // (T,B,F)
    const float* wih  = (const float*)d_in[1];   // (3H,F)
    const float* whh  = (const float*)d_in[2];   // (3H,H)
    const float* bih  = (const float*)d_in[3];   // (3H)
    const float* bhh  = (const float*)d_in[4];   // (3H)
    const float* wout = (const float*)d_in[5];   // (O,H)
    const float* bout = (const float*)d_in[6];   // (O)
    float* y = (float*)d_out;                    // (T,B,O)

    cudaFuncSetAttribute(k2_gru, cudaFuncAttributeMaxDynamicSharedMemorySize,
                         SMEM2_BYTES);

    // 1) xg = x @ w_ih^T + b_ih  (HMMA split-bf16)
    k1_xg<<<dim3(G_SZ / 64, (T_STEPS * B_SZ) / 128), 256>>>(x, wih, bih);

    // 2) persistent GRU recurrence (HMMA, 2-D tiled, 2 barrier groups)
    k2_gru<<<NCTA2, NTHR2, SMEM2_BYTES>>>(whh, bhh);

    // 3) output projection
    k3_out<<<(T_STEPS * B_SZ) / 128, 128>>>(wout, bout, y);
}